// round 6
// baseline (speedup 1.0000x reference)
#include <cuda_runtime.h>
#include <cuda_fp16.h>
#include <cuda_bf16.h>
#include <cstdint>

// ---------------- problem constants ----------------
#define DM     1024
#define NLAYER 2
#define VOCAB  32000
#define DS     16
#define DI     2048
#define DR     64
#define DC     4
#define BB     2
#define LL     1024
#define TT     (BB*LL)

// ---------------- device scratch (fp32) ----------------
__device__ float g_x   [TT*DM];
__device__ float g_xi  [TT*DI];
__device__ float g_res [TT*DI];
__device__ float g_u   [TT*DI];
__device__ float g_xdbl[TT*96];
__device__ float g_dlt [TT*DI];

// ---------------- fp16 buffers: A-side split (hi+lo), B-side plain ----------------
__device__ __half g_emb_f[VOCAB*DM];
__device__ __half g_xn_h [TT*DM],  g_xn_l [TT*DM];
__device__ __half g_u_h  [TT*DI],  g_u_l  [TT*DI];
__device__ __half g_xd_h [TT*96],  g_xd_l [TT*96];
__device__ __half g_y_h  [TT*DI],  g_y_l  [TT*DI];
__device__ __half g_w_f  [DI*DM];

// ---------------- helpers ----------------
static __device__ __forceinline__ uint32_t s2u(const void* p) {
    uint32_t a;
    asm("{ .reg .u64 t; cvta.to.shared.u64 t, %1; cvt.u32.u64 %0, t; }" : "=r"(a) : "l"(p));
    return a;
}
static __device__ __forceinline__ void cp16(uint32_t s, const void* g, bool pred) {
    int sz = pred ? 16 : 0;
    asm volatile("cp.async.cg.shared.global [%0], [%1], 16, %2;" :: "r"(s), "l"(g), "r"(sz));
}
#define CP_COMMIT() asm volatile("cp.async.commit_group;" ::: "memory")
#define CP_WAIT1()  asm volatile("cp.async.wait_group 1;"  ::: "memory")

#define LDSM4(r, addr) asm volatile( \
    "ldmatrix.sync.aligned.m8n8.x4.shared.b16 {%0,%1,%2,%3}, [%4];" \
    : "=r"((r)[0]),"=r"((r)[1]),"=r"((r)[2]),"=r"((r)[3]) : "r"(addr))
#define MMA(d, a, b) asm volatile( \
    "mma.sync.aligned.m16n8k16.row.col.f32.f16.f16.f32 " \
    "{%0,%1,%2,%3},{%4,%5,%6,%7},{%8,%9},{%0,%1,%2,%3};" \
    : "+f"((d)[0]),"+f"((d)[1]),"+f"((d)[2]),"+f"((d)[3]) \
    : "r"((a)[0]),"r"((a)[1]),"r"((a)[2]),"r"((a)[3]),"r"((b)[0]),"r"((b)[1]))

// ---------------- embed ----------------
__global__ void k_embed(const int* __restrict__ ids, const float* __restrict__ emb) {
    int t = blockIdx.x;
    int id = ids[t];
    for (int c = threadIdx.x; c < DM; c += blockDim.x)
        g_x[t*DM + c] = emb[id*DM + c];
}

// ---------------- rmsnorm -> fp16 hi/lo split ----------------
__global__ void k_rmsnorm(const float* __restrict__ x, const float* __restrict__ w,
                          __half* __restrict__ oh, __half* __restrict__ ol) {
    int t = blockIdx.x;
    const float* xr = x + t*DM;
    float s = 0.f;
    for (int c = threadIdx.x; c < DM; c += blockDim.x) { float v = xr[c]; s += v*v; }
    for (int o = 16; o > 0; o >>= 1) s += __shfl_xor_sync(0xffffffffu, s, o);
    __shared__ float red[8];
    int wid = threadIdx.x >> 5, lid = threadIdx.x & 31;
    if (lid == 0) red[wid] = s;
    __syncthreads();
    if (wid == 0) {
        float v = (lid < (blockDim.x >> 5)) ? red[lid] : 0.f;
        for (int o = 4; o > 0; o >>= 1) v += __shfl_xor_sync(0xffffffffu, v, o);
        if (lid == 0) red[0] = v;
    }
    __syncthreads();
    float scale = rsqrtf(red[0] / (float)DM + 1e-5f);
    for (int c = threadIdx.x; c < DM; c += blockDim.x) {
        float v = xr[c] * scale * w[c];
        __half h = __float2half_rn(v);
        oh[t*DM + c] = h;
        ol[t*DM + c] = __float2half_rn(v - __half2float(h));
    }
}

// ---------------- fp32 -> fp16 hi/lo split ----------------
__global__ void k_split(const float* __restrict__ x, __half* __restrict__ h,
                        __half* __restrict__ l, int n) {
    int i = (blockIdx.x * blockDim.x + threadIdx.x) * 4;
    if (i >= n) return;
    float4 v = *reinterpret_cast<const float4*>(x + i);
    __half h0 = __float2half_rn(v.x), h1 = __float2half_rn(v.y);
    __half h2 = __float2half_rn(v.z), h3 = __float2half_rn(v.w);
    __half2 H0, H1, L0, L1;
    H0.x = h0; H0.y = h1; H1.x = h2; H1.y = h3;
    L0.x = __float2half_rn(v.x - __half2float(h0));
    L0.y = __float2half_rn(v.y - __half2float(h1));
    L1.x = __float2half_rn(v.z - __half2float(h2));
    L1.y = __float2half_rn(v.w - __half2float(h3));
    *reinterpret_cast<uint2*>(h + i) =
        make_uint2(*reinterpret_cast<uint32_t*>(&H0), *reinterpret_cast<uint32_t*>(&H1));
    *reinterpret_cast<uint2*>(l + i) =
        make_uint2(*reinterpret_cast<uint32_t*>(&L0), *reinterpret_cast<uint32_t*>(&L1));
}

// ---------------- fp32 -> fp16 plain convert ----------------
__global__ void k_cvt(const float* __restrict__ x, __half* __restrict__ o, int n) {
    int i = (blockIdx.x * blockDim.x + threadIdx.x) * 8;
    if (i >= n) return;
    float4 a = *reinterpret_cast<const float4*>(x + i);
    float4 b = *reinterpret_cast<const float4*>(x + i + 4);
    __half2 p0, p1, p2, p3;
    p0.x = __float2half_rn(a.x); p0.y = __float2half_rn(a.y);
    p1.x = __float2half_rn(a.z); p1.y = __float2half_rn(a.w);
    p2.x = __float2half_rn(b.x); p2.y = __float2half_rn(b.y);
    p3.x = __float2half_rn(b.z); p3.y = __float2half_rn(b.w);
    uint4 pk;
    pk.x = *reinterpret_cast<uint32_t*>(&p0);
    pk.y = *reinterpret_cast<uint32_t*>(&p1);
    pk.z = *reinterpret_cast<uint32_t*>(&p2);
    pk.w = *reinterpret_cast<uint32_t*>(&p3);
    *reinterpret_cast<uint4*>(o + i) = pk;
}

// ---------------- HMMA GEMM: C[M,N] = A[M,K] @ B[N,K]^T, fp16 2-term ----------------
// CTA tile 128m x 256n, 8 warps (2x4), warp tile 64x64
#define EPI_NONE     0
#define EPI_SOFTPLUS 1
#define EPI_RESADD   2

#define A_TILE   8192          // 128 rows x 64 bytes (BK=32 fp16)
#define B_TILE   16384         // 256 rows x 64 bytes
#define OFF_AH   0
#define OFF_AL   (A_TILE)
#define OFF_BF   (2*A_TILE)
#define STAGE_B  (2*A_TILE + B_TILE)   // 32 KB
#define NSTAGE   3
#define SMEM_DYN (NSTAGE*STAGE_B)      // 96 KB

__device__ __forceinline__ void load_stage(uint32_t sbase,
        const __half* __restrict__ Ah, const __half* __restrict__ Al,
        int lda, int m0,
        const __half* __restrict__ Bf,
        int ldb, int n0, int N, int k0, int tid) {
    // A: 128 rows x 4 chunks = 512 slots, 256 threads x 2
    #pragma unroll
    for (int it = 0; it < 2; it++) {
        int i = tid + it*256;
        int r = i >> 2;
        int cby = (i & 3) * 16;
        uint32_t off = r*64 + (cby ^ (((r >> 1) & 3) << 4));
        size_t ga = (size_t)(m0 + r)*lda + k0 + (i & 3)*8;
        cp16(sbase + OFF_AH + off, Ah + ga, true);
        cp16(sbase + OFF_AL + off, Al + ga, true);
    }
    // B: 256 rows x 4 chunks = 1024 slots, 256 threads x 4
    #pragma unroll
    for (int it = 0; it < 4; it++) {
        int i = tid + it*256;
        int r = i >> 2;
        int cby = (i & 3) * 16;
        uint32_t off = r*64 + (cby ^ (((r >> 1) & 3) << 4));
        bool bp = (n0 + r) < N;
        size_t gb = (size_t)(bp ? (n0 + r) : 0)*ldb + k0 + (i & 3)*8;
        cp16(sbase + OFF_BF + off, Bf + gb, bp);
    }
}

template<int EPI>
__global__ void __launch_bounds__(256, 1) k_mma(
        const __half* __restrict__ Ah, const __half* __restrict__ Al, int lda,
        const __half* __restrict__ Bf, int ldb,
        float* __restrict__ C, int ldc, int M, int N, int K,
        const float* __restrict__ R) {
    extern __shared__ __align__(1024) char smem[];
    const uint32_t sb = s2u(smem);
    const int tid = threadIdx.x, lane = tid & 31, wid = tid >> 5;
    const int wm = wid >> 2, wn = wid & 3;       // 2 x 4 warp grid, 64x64 per warp
    const int m0 = blockIdx.x * 128, n0 = blockIdx.y * 256;

    float acc[4][8][4];
    #pragma unroll
    for (int a = 0; a < 4; a++)
        #pragma unroll
        for (int b = 0; b < 8; b++)
            #pragma unroll
            for (int c = 0; c < 4; c++) acc[a][b][c] = 0.f;

    const int NC = K / 32;
    load_stage(sb + 0*STAGE_B, Ah, Al, lda, m0, Bf, ldb, n0, N,  0, tid); CP_COMMIT();
    if (NC > 1) load_stage(sb + 1*STAGE_B, Ah, Al, lda, m0, Bf, ldb, n0, N, 32, tid);
    CP_COMMIT();

    const int arow = lane & 15;
    const int acb  = ((lane >> 4) & 1) * 16;
    const int brow = lane & 7;
    const int bnt  = (lane >> 4) & 1;
    const int bkh  = (lane >> 3) & 1;

    int stage = 0;
    for (int c = 0; c < NC; c++) {
        CP_WAIT1();
        __syncthreads();
        if (c + 2 < NC) {
            int s2 = stage + 2; if (s2 >= NSTAGE) s2 -= NSTAGE;
            load_stage(sb + s2*STAGE_B, Ah, Al, lda, m0, Bf, ldb, n0, N,
                       (c + 2)*32, tid);
        }
        CP_COMMIT();

        uint32_t st = sb + stage*STAGE_B;
        #pragma unroll
        for (int kk = 0; kk < 2; kk++) {
            uint32_t bf[8][2], ah[4][4], al[4][4];
            #pragma unroll
            for (int p = 0; p < 4; p++) {
                int r = wn*64 + (p*2 + bnt)*8 + brow;
                uint32_t off = r*64 + (((kk*2 + bkh)*16) ^ (((r >> 1) & 3) << 4));
                uint32_t t[4];
                LDSM4(t, st + OFF_BF + off);
                bf[2*p][0] = t[0]; bf[2*p][1] = t[1];
                bf[2*p+1][0] = t[2]; bf[2*p+1][1] = t[3];
            }
            #pragma unroll
            for (int mt = 0; mt < 4; mt++) {
                int r = wm*64 + mt*16 + arow;
                uint32_t off = r*64 + ((kk*32 + acb) ^ (((r >> 1) & 3) << 4));
                LDSM4(ah[mt], st + OFF_AH + off);
                LDSM4(al[mt], st + OFF_AL + off);
            }
            #pragma unroll
            for (int mt = 0; mt < 4; mt++)
                #pragma unroll
                for (int nt = 0; nt < 8; nt++)
                    MMA(acc[mt][nt], ah[mt], bf[nt]);
            #pragma unroll
            for (int mt = 0; mt < 4; mt++)
                #pragma unroll
                for (int nt = 0; nt < 8; nt++)
                    MMA(acc[mt][nt], al[mt], bf[nt]);
        }
        stage++; if (stage >= NSTAGE) stage = 0;
    }

    // epilogue
    #pragma unroll
    for (int mt = 0; mt < 4; mt++) {
        #pragma unroll
        for (int nt = 0; nt < 8; nt++) {
            int row = m0 + wm*64 + mt*16 + (lane >> 2);
            int col = n0 + wn*64 + nt*8 + (lane & 3)*2;
            if (col < N) {
                #pragma unroll
                for (int h = 0; h < 2; h++) {
                    int rr = row + h*8;
                    float v0 = acc[mt][nt][2*h + 0];
                    float v1 = acc[mt][nt][2*h + 1];
                    if (EPI == EPI_SOFTPLUS) {
                        v0 = (v0 > 20.f) ? v0 : log1pf(expf(v0));
                        v1 = (v1 > 20.f) ? v1 : log1pf(expf(v1));
                    }
                    if (EPI == EPI_RESADD) {
                        v0 += R[(size_t)rr*ldc + col];
                        v1 += R[(size_t)rr*ldc + col + 1];
                    }
                    *reinterpret_cast<float2*>(&C[(size_t)rr*ldc + col]) = make_float2(v0, v1);
                }
            }
        }
    }
}

// ---------------- depthwise causal conv + bias + SiLU ----------------
__global__ void k_conv_silu(const float* __restrict__ cw, const float* __restrict__ cb) {
    int idx = blockIdx.x * blockDim.x + threadIdx.x;
    if (idx >= TT*DI) return;
    int d = idx % DI;
    int l = (idx / DI) % LL;
    int b = idx / (DI*LL);
    float acc = cb[d];
    #pragma unroll
    for (int j = 0; j < DC; j++) {
        int ll = l - (DC-1) + j;
        if (ll >= 0) acc = fmaf(cw[d*DC + j], g_xi[((size_t)b*LL + ll)*DI + d], acc);
    }
    float s = acc / (1.f + __expf(-acc));
    g_u[idx] = s;
    __half h = __float2half_rn(s);
    g_u_h[idx] = h;
    g_u_l[idx] = __float2half_rn(s - __half2float(h));
}

// ---------------- selective scan + gate ----------------
__global__ void k_scan(const float* __restrict__ A_log, const float* __restrict__ Dp) {
    int lane = threadIdx.x & 15;
    int grp  = threadIdx.x >> 4;
    int ch   = blockIdx.x * 16 + grp;
    int b = ch / DI, d = ch % DI;

    float An = -__expf(A_log[d*DS + lane]);
    float Dv = Dp[d];
    float xs = 0.f;

    for (int l = 0; l < LL; l++) {
        int tok = b*LL + l;
        float dlt = g_dlt[(size_t)tok*DI + d];
        float uu  = g_u  [(size_t)tok*DI + d];
        float Bn  = g_xdbl[(size_t)tok*96 + 64 + lane];
        float Cn  = g_xdbl[(size_t)tok*96 + 80 + lane];
        float dA  = __expf(dlt * An);
        xs = fmaf(dA, xs, dlt * uu * Bn);
        float yv = xs * Cn;
        yv += __shfl_xor_sync(0xffffffffu, yv, 8);
        yv += __shfl_xor_sync(0xffffffffu, yv, 4);
        yv += __shfl_xor_sync(0xffffffffu, yv, 2);
        yv += __shfl_xor_sync(0xffffffffu, yv, 1);
        if (lane == 0) {
            float r = g_res[(size_t)tok*DI + d];
            float gate = r / (1.f + __expf(-r));
            float v = (yv + uu * Dv) * gate;
            __half h = __float2half_rn(v);
            g_y_h[(size_t)tok*DI + d] = h;
            g_y_l[(size_t)tok*DI + d] = __float2half_rn(v - __half2float(h));
        }
    }
}

// ---------------- launch ----------------
extern "C" void kernel_launch(void* const* d_in, const int* in_sizes, int n_in,
                              void* d_out, int out_size) {
    const int*   ids      = (const int*)  d_in[0];
    const float* emb      = (const float*)d_in[1];
    const float* norm_f_w = (const float*)d_in[2];
    const float* W_in_l   = (const float*)d_in[3];
    const float* W_in_r   = (const float*)d_in[4];
    const float* conv_w   = (const float*)d_in[5];
    const float* conv_b   = (const float*)d_in[6];
    const float* W_x      = (const float*)d_in[7];
    const float* W_dt     = (const float*)d_in[8];
    const float* A_log    = (const float*)d_in[9];
    const float* Dp       = (const float*)d_in[10];
    const float* W_out    = (const float*)d_in[11];
    const float* norm_w   = (const float*)d_in[12];
    float* out = (float*)d_out;

    float *p_x, *p_xi, *p_res, *p_u, *p_xdbl, *p_dlt;
    cudaGetSymbolAddress((void**)&p_x,    g_x);
    cudaGetSymbolAddress((void**)&p_xi,   g_xi);
    cudaGetSymbolAddress((void**)&p_res,  g_res);
    cudaGetSymbolAddress((void**)&p_u,    g_u);
    cudaGetSymbolAddress((void**)&p_xdbl, g_xdbl);
    cudaGetSymbolAddress((void**)&p_dlt,  g_dlt);

    __half *p_ef, *p_xnh, *p_xnl, *p_uh, *p_ul, *p_xdh, *p_xdl, *p_yh, *p_yl, *p_wf;
    cudaGetSymbolAddress((void**)&p_ef,  g_emb_f);
    cudaGetSymbolAddress((void**)&p_xnh, g_xn_h);
    cudaGetSymbolAddress((void**)&p_xnl, g_xn_l);
    cudaGetSymbolAddress((void**)&p_uh,  g_u_h);
    cudaGetSymbolAddress((void**)&p_ul,  g_u_l);
    cudaGetSymbolAddress((void**)&p_xdh, g_xd_h);
    cudaGetSymbolAddress((void**)&p_xdl, g_xd_l);
    cudaGetSymbolAddress((void**)&p_yh,  g_y_h);
    cudaGetSymbolAddress((void**)&p_yl,  g_y_l);
    cudaGetSymbolAddress((void**)&p_wf,  g_w_f);

    cudaFuncSetAttribute(k_mma<EPI_NONE>,     cudaFuncAttributeMaxDynamicSharedMemorySize, SMEM_DYN);
    cudaFuncSetAttribute(k_mma<EPI_SOFTPLUS>, cudaFuncAttributeMaxDynamicSharedMemorySize, SMEM_DYN);
    cudaFuncSetAttribute(k_mma<EPI_RESADD>,   cudaFuncAttributeMaxDynamicSharedMemorySize, SMEM_DYN);

    k_embed<<<TT, 256>>>(ids, emb);
    k_cvt<<<(VOCAB*DM/8 + 255)/256, 256>>>(emb, p_ef, VOCAB*DM);

    for (int i = 0; i < NLAYER; i++) {
        const float* Wl  = W_in_l + (size_t)i*DI*DM;
        const float* Wr  = W_in_r + (size_t)i*DI*DM;
        const float* cw  = conv_w + (size_t)i*DI*DC;
        const float* cb  = conv_b + (size_t)i*DI;
        const float* Wx  = W_x    + (size_t)i*(DR+2*DS)*DI;
        const float* Wdt = W_dt   + (size_t)i*DI*DR;
        const float* Al  = A_log  + (size_t)i*DI*DS;
        const float* Dpi = Dp     + (size_t)i*DI;
        const float* Wo  = W_out  + (size_t)i*DM*DI;
        const float* nw  = norm_w + (size_t)i*DM;

        k_rmsnorm<<<TT, 256>>>(p_x, nw, p_xnh, p_xnl);

        // xi = xn @ Wl^T   (2048 x 2048, K=1024)
        k_cvt<<<(DI*DM/8 + 255)/256, 256>>>(Wl, p_wf, DI*DM);
        k_mma<EPI_NONE><<<dim3(TT/128, DI/256), 256, SMEM_DYN>>>(
            p_xnh, p_xnl, DM, p_wf, DM, p_xi, DI, TT, DI, DM, nullptr);

        // res = xn @ Wr^T
        k_cvt<<<(DI*DM/8 + 255)/256, 256>>>(Wr, p_wf, DI*DM);
        k_mma<EPI_NONE><<<dim3(TT/128, DI/256), 256, SMEM_DYN>>>(
            p_xnh, p_xnl, DM, p_wf, DM, p_res, DI, TT, DI, DM, nullptr);

        k_conv_silu<<<(TT*DI + 255)/256, 256>>>(cw, cb);

        // x_dbl = u @ Wx^T  (2048 x 96, K=2048)
        k_cvt<<<(96*DI/8 + 255)/256, 256>>>(Wx, p_wf, 96*DI);
        k_mma<EPI_NONE><<<dim3(TT/128, 1), 256, SMEM_DYN>>>(
            p_uh, p_ul, DI, p_wf, DI, p_xdbl, 96, TT, 96, DI, nullptr);

        k_split<<<(TT*96/4 + 255)/256, 256>>>(p_xdbl, p_xdh, p_xdl, TT*96);

        // delta = softplus(x_dbl[:, :64] @ Wdt^T)  (2048 x 2048, K=64)
        k_cvt<<<(DI*DR/8 + 255)/256, 256>>>(Wdt, p_wf, DI*DR);
        k_mma<EPI_SOFTPLUS><<<dim3(TT/128, DI/256), 256, SMEM_DYN>>>(
            p_xdh, p_xdl, 96, p_wf, DR, p_dlt, DI, TT, DI, DR, nullptr);

        k_scan<<<(BB*DI)/16, 256>>>(Al, Dpi);

        // x = y @ Wo^T + x  (2048 x 1024, K=2048)
        k_cvt<<<(DM*DI/8 + 255)/256, 256>>>(Wo, p_wf, DM*DI);
        k_mma<EPI_RESADD><<<dim3(TT/128, DM/256), 256, SMEM_DYN>>>(
            p_yh, p_yl, DI, p_wf, DI, p_x, DM, TT, DM, DI, p_x);
    }

    // final norm + logits (2048 x 32000, K=1024)
    k_rmsnorm<<<TT, 256>>>(p_x, norm_f_w, p_xnh, p_xnl);
    k_mma<EPI_NONE><<<dim3(TT/128, VOCAB/256), 256, SMEM_DYN>>>(
        p_xnh, p_xnl, DM, p_ef, DM, out, VOCAB, TT, VOCAB, DM, nullptr);
}

// round 7
// speedup vs baseline: 1.0708x; 1.0708x over previous
#include <cuda_runtime.h>
#include <cuda_fp16.h>
#include <cuda_bf16.h>
#include <cstdint>

// ---------------- problem constants ----------------
#define DM     1024
#define NLAYER 2
#define VOCAB  32000
#define DS     16
#define DI     2048
#define DR     64
#define DC     4
#define BB     2
#define LL     1024
#define TT     (BB*LL)

// ---------------- device scratch (fp32) ----------------
__device__ float g_x   [TT*DM];
__device__ float g_ir  [TT*2*DI];    // [xi(2048) | res(2048)] fused in-proj output
__device__ float g_u   [TT*DI];
__device__ float g_xdbl[TT*96];
__device__ float g_dlt [TT*DI];

// ---------------- fp16 buffers: A-side split (hi+lo), B-side plain ----------------
__device__ __half g_emb_f[VOCAB*DM];
__device__ __half g_xn_h [TT*DM],  g_xn_l [TT*DM];
__device__ __half g_u_h  [TT*DI],  g_u_l  [TT*DI];
__device__ __half g_xd_h [TT*96],  g_xd_l [TT*96];
__device__ __half g_y_h  [TT*DI],  g_y_l  [TT*DI];
__device__ __half g_w_f  [2*DI*DM];   // room for Wl+Wr fused

// ---------------- helpers ----------------
static __device__ __forceinline__ uint32_t s2u(const void* p) {
    uint32_t a;
    asm("{ .reg .u64 t; cvta.to.shared.u64 t, %1; cvt.u32.u64 %0, t; }" : "=r"(a) : "l"(p));
    return a;
}
static __device__ __forceinline__ void cp16(uint32_t s, const void* g, bool pred) {
    int sz = pred ? 16 : 0;
    asm volatile("cp.async.cg.shared.global [%0], [%1], 16, %2;" :: "r"(s), "l"(g), "r"(sz));
}
#define CP_COMMIT() asm volatile("cp.async.commit_group;" ::: "memory")
#define CP_WAIT2()  asm volatile("cp.async.wait_group 2;"  ::: "memory")

#define LDSM4(r, addr) asm volatile( \
    "ldmatrix.sync.aligned.m8n8.x4.shared.b16 {%0,%1,%2,%3}, [%4];" \
    : "=r"((r)[0]),"=r"((r)[1]),"=r"((r)[2]),"=r"((r)[3]) : "r"(addr))
#define MMA(d, a, b) asm volatile( \
    "mma.sync.aligned.m16n8k16.row.col.f32.f16.f16.f32 " \
    "{%0,%1,%2,%3},{%4,%5,%6,%7},{%8,%9},{%0,%1,%2,%3};" \
    : "+f"((d)[0]),"+f"((d)[1]),"+f"((d)[2]),"+f"((d)[3]) \
    : "r"((a)[0]),"r"((a)[1]),"r"((a)[2]),"r"((a)[3]),"r"((b)[0]),"r"((b)[1]))

// ---------------- embed ----------------
__global__ void k_embed(const int* __restrict__ ids, const float* __restrict__ emb) {
    int t = blockIdx.x;
    int id = ids[t];
    for (int c = threadIdx.x; c < DM; c += blockDim.x)
        g_x[t*DM + c] = emb[id*DM + c];
}

// ---------------- rmsnorm -> fp16 hi/lo split ----------------
__global__ void k_rmsnorm(const float* __restrict__ x, const float* __restrict__ w,
                          __half* __restrict__ oh, __half* __restrict__ ol) {
    int t = blockIdx.x;
    const float* xr = x + t*DM;
    float s = 0.f;
    for (int c = threadIdx.x; c < DM; c += blockDim.x) { float v = xr[c]; s += v*v; }
    for (int o = 16; o > 0; o >>= 1) s += __shfl_xor_sync(0xffffffffu, s, o);
    __shared__ float red[8];
    int wid = threadIdx.x >> 5, lid = threadIdx.x & 31;
    if (lid == 0) red[wid] = s;
    __syncthreads();
    if (wid == 0) {
        float v = (lid < (blockDim.x >> 5)) ? red[lid] : 0.f;
        for (int o = 4; o > 0; o >>= 1) v += __shfl_xor_sync(0xffffffffu, v, o);
        if (lid == 0) red[0] = v;
    }
    __syncthreads();
    float scale = rsqrtf(red[0] / (float)DM + 1e-5f);
    for (int c = threadIdx.x; c < DM; c += blockDim.x) {
        float v = xr[c] * scale * w[c];
        __half h = __float2half_rn(v);
        oh[t*DM + c] = h;
        ol[t*DM + c] = __float2half_rn(v - __half2float(h));
    }
}

// ---------------- fp32 -> fp16 hi/lo split ----------------
__global__ void k_split(const float* __restrict__ x, __half* __restrict__ h,
                        __half* __restrict__ l, int n) {
    int i = (blockIdx.x * blockDim.x + threadIdx.x) * 4;
    if (i >= n) return;
    float4 v = *reinterpret_cast<const float4*>(x + i);
    __half h0 = __float2half_rn(v.x), h1 = __float2half_rn(v.y);
    __half h2 = __float2half_rn(v.z), h3 = __float2half_rn(v.w);
    __half2 H0, H1, L0, L1;
    H0.x = h0; H0.y = h1; H1.x = h2; H1.y = h3;
    L0.x = __float2half_rn(v.x - __half2float(h0));
    L0.y = __float2half_rn(v.y - __half2float(h1));
    L1.x = __float2half_rn(v.z - __half2float(h2));
    L1.y = __float2half_rn(v.w - __half2float(h3));
    *reinterpret_cast<uint2*>(h + i) =
        make_uint2(*reinterpret_cast<uint32_t*>(&H0), *reinterpret_cast<uint32_t*>(&H1));
    *reinterpret_cast<uint2*>(l + i) =
        make_uint2(*reinterpret_cast<uint32_t*>(&L0), *reinterpret_cast<uint32_t*>(&L1));
}

// ---------------- fp32 -> fp16 plain convert ----------------
__global__ void k_cvt(const float* __restrict__ x, __half* __restrict__ o, int n) {
    int i = (blockIdx.x * blockDim.x + threadIdx.x) * 8;
    if (i >= n) return;
    float4 a = *reinterpret_cast<const float4*>(x + i);
    float4 b = *reinterpret_cast<const float4*>(x + i + 4);
    __half2 p0, p1, p2, p3;
    p0.x = __float2half_rn(a.x); p0.y = __float2half_rn(a.y);
    p1.x = __float2half_rn(a.z); p1.y = __float2half_rn(a.w);
    p2.x = __float2half_rn(b.x); p2.y = __float2half_rn(b.y);
    p3.x = __float2half_rn(b.z); p3.y = __float2half_rn(b.w);
    uint4 pk;
    pk.x = *reinterpret_cast<uint32_t*>(&p0);
    pk.y = *reinterpret_cast<uint32_t*>(&p1);
    pk.z = *reinterpret_cast<uint32_t*>(&p2);
    pk.w = *reinterpret_cast<uint32_t*>(&p3);
    *reinterpret_cast<uint4*>(o + i) = pk;
}

// ---------------- HMMA GEMM: C[M,N] = A[M,K] @ B[N,K]^T, fp16 2-term ----------------
#define EPI_NONE     0
#define EPI_SOFTPLUS 1
#define EPI_RESADD   2

#define TILE_B   8192          // 128 rows x 64 bytes (BK=32 fp16)
#define OFF_AH   0
#define OFF_AL   (1*TILE_B)
#define OFF_BF   (2*TILE_B)
#define STAGE_B  (3*TILE_B)    // 24 KB
#define NSTAGE   4
#define SMEM_DYN (NSTAGE*STAGE_B)   // 96 KB

__device__ __forceinline__ void load_stage(uint32_t sbase,
        const __half* __restrict__ Ah, const __half* __restrict__ Al,
        int lda, int m0,
        const __half* __restrict__ Bf,
        int ldb, int n0, int N, int k0, int tid) {
    #pragma unroll
    for (int it = 0; it < 2; it++) {
        int i = tid + it*256;
        int r = i >> 2;
        int cby = (i & 3) * 16;
        uint32_t off = r*64 + (cby ^ (((r >> 1) & 3) << 4));
        size_t ga = (size_t)(m0 + r)*lda + k0 + (i & 3)*8;
        cp16(sbase + OFF_AH + off, Ah + ga, true);
        cp16(sbase + OFF_AL + off, Al + ga, true);
        bool bp = (n0 + r) < N;
        size_t gb = (size_t)(bp ? (n0 + r) : 0)*ldb + k0 + (i & 3)*8;
        cp16(sbase + OFF_BF + off, Bf + gb, bp);
    }
}

template<int EPI>
__global__ void __launch_bounds__(256, 2) k_mma(
        const __half* __restrict__ Ah, const __half* __restrict__ Al, int lda,
        const __half* __restrict__ Bf, int ldb,
        float* __restrict__ C, int ldc, int M, int N, int K,
        const float* __restrict__ R) {
    extern __shared__ __align__(1024) char smem[];
    const uint32_t sb = s2u(smem);
    const int tid = threadIdx.x, lane = tid & 31, wid = tid >> 5;
    const int wm = wid >> 2, wn = wid & 3;       // 2 x 4 warp grid, 64x32 per warp
    const int m0 = blockIdx.x * 128, n0 = blockIdx.y * 128;

    float acc[4][4][4];
    #pragma unroll
    for (int a = 0; a < 4; a++)
        #pragma unroll
        for (int b = 0; b < 4; b++)
            #pragma unroll
            for (int c = 0; c < 4; c++) acc[a][b][c] = 0.f;

    const int NC = K / 32;
    #pragma unroll
    for (int p = 0; p < 3; p++) {
        if (p < NC)
            load_stage(sb + p*STAGE_B, Ah, Al, lda, m0, Bf, ldb, n0, N, p*32, tid);
        CP_COMMIT();
    }

    const int arow = lane & 15;
    const int acb  = ((lane >> 4) & 1) * 16;
    const int brow = lane & 7;
    const int bnt  = (lane >> 4) & 1;
    const int bkh  = (lane >> 3) & 1;

    int stage = 0;
    for (int c = 0; c < NC; c++) {
        CP_WAIT2();
        __syncthreads();
        if (c + 3 < NC) {
            int s3 = stage + 3; if (s3 >= NSTAGE) s3 -= NSTAGE;
            load_stage(sb + s3*STAGE_B, Ah, Al, lda, m0, Bf, ldb, n0, N,
                       (c + 3)*32, tid);
        }
        CP_COMMIT();

        uint32_t st = sb + stage*STAGE_B;
        #pragma unroll
        for (int kk = 0; kk < 2; kk++) {
            uint32_t bf[4][2], af[4][4];
            #pragma unroll
            for (int p = 0; p < 2; p++) {
                int r = wn*32 + (p*2 + bnt)*8 + brow;
                uint32_t off = r*64 + (((kk*2 + bkh)*16) ^ (((r >> 1) & 3) << 4));
                uint32_t t[4];
                LDSM4(t, st + OFF_BF + off);
                bf[2*p][0] = t[0]; bf[2*p][1] = t[1];
                bf[2*p+1][0] = t[2]; bf[2*p+1][1] = t[3];
            }
            // hi term
            #pragma unroll
            for (int mt = 0; mt < 4; mt++) {
                int r = wm*64 + mt*16 + arow;
                uint32_t off = r*64 + ((kk*32 + acb) ^ (((r >> 1) & 3) << 4));
                LDSM4(af[mt], st + OFF_AH + off);
            }
            #pragma unroll
            for (int mt = 0; mt < 4; mt++)
                #pragma unroll
                for (int nt = 0; nt < 4; nt++)
                    MMA(acc[mt][nt], af[mt], bf[nt]);
            // lo term (reuse af regs)
            #pragma unroll
            for (int mt = 0; mt < 4; mt++) {
                int r = wm*64 + mt*16 + arow;
                uint32_t off = r*64 + ((kk*32 + acb) ^ (((r >> 1) & 3) << 4));
                LDSM4(af[mt], st + OFF_AL + off);
            }
            #pragma unroll
            for (int mt = 0; mt < 4; mt++)
                #pragma unroll
                for (int nt = 0; nt < 4; nt++)
                    MMA(acc[mt][nt], af[mt], bf[nt]);
        }
        stage++; if (stage >= NSTAGE) stage = 0;
    }

    // epilogue
    #pragma unroll
    for (int mt = 0; mt < 4; mt++) {
        #pragma unroll
        for (int nt = 0; nt < 4; nt++) {
            int row = m0 + wm*64 + mt*16 + (lane >> 2);
            int col = n0 + wn*32 + nt*8 + (lane & 3)*2;
            if (col < N) {
                #pragma unroll
                for (int h = 0; h < 2; h++) {
                    int rr = row + h*8;
                    float v0 = acc[mt][nt][2*h + 0];
                    float v1 = acc[mt][nt][2*h + 1];
                    if (EPI == EPI_SOFTPLUS) {
                        v0 = (v0 > 20.f) ? v0 : log1pf(expf(v0));
                        v1 = (v1 > 20.f) ? v1 : log1pf(expf(v1));
                    }
                    if (EPI == EPI_RESADD) {
                        v0 += R[(size_t)rr*ldc + col];
                        v1 += R[(size_t)rr*ldc + col + 1];
                    }
                    *reinterpret_cast<float2*>(&C[(size_t)rr*ldc + col]) = make_float2(v0, v1);
                }
            }
        }
    }
}

// ---------------- depthwise causal conv + bias + SiLU ----------------
__global__ void k_conv_silu(const float* __restrict__ cw, const float* __restrict__ cb) {
    int idx = blockIdx.x * blockDim.x + threadIdx.x;
    if (idx >= TT*DI) return;
    int d = idx % DI;
    int l = (idx / DI) % LL;
    int b = idx / (DI*LL);
    float acc = cb[d];
    #pragma unroll
    for (int j = 0; j < DC; j++) {
        int ll = l - (DC-1) + j;
        if (ll >= 0) acc = fmaf(cw[d*DC + j], g_ir[((size_t)b*LL + ll)*(2*DI) + d], acc);
    }
    float s = acc / (1.f + __expf(-acc));
    g_u[idx] = s;
    __half h = __float2half_rn(s);
    g_u_h[idx] = h;
    g_u_l[idx] = __float2half_rn(s - __half2float(h));
}

// ---------------- selective scan + gate ----------------
__global__ void k_scan(const float* __restrict__ A_log, const float* __restrict__ Dp) {
    int lane = threadIdx.x & 15;
    int grp  = threadIdx.x >> 4;
    int ch   = blockIdx.x * 16 + grp;
    int b = ch / DI, d = ch % DI;

    float An = -__expf(A_log[d*DS + lane]);
    float Dv = Dp[d];
    float xs = 0.f;

    for (int l = 0; l < LL; l++) {
        int tok = b*LL + l;
        float dlt = g_dlt[(size_t)tok*DI + d];
        float uu  = g_u  [(size_t)tok*DI + d];
        float Bn  = g_xdbl[(size_t)tok*96 + 64 + lane];
        float Cn  = g_xdbl[(size_t)tok*96 + 80 + lane];
        float dA  = __expf(dlt * An);
        xs = fmaf(dA, xs, dlt * uu * Bn);
        float yv = xs * Cn;
        yv += __shfl_xor_sync(0xffffffffu, yv, 8);
        yv += __shfl_xor_sync(0xffffffffu, yv, 4);
        yv += __shfl_xor_sync(0xffffffffu, yv, 2);
        yv += __shfl_xor_sync(0xffffffffu, yv, 1);
        if (lane == 0) {
            float r = g_ir[(size_t)tok*(2*DI) + DI + d];
            float gate = r / (1.f + __expf(-r));
            float v = (yv + uu * Dv) * gate;
            __half h = __float2half_rn(v);
            g_y_h[(size_t)tok*DI + d] = h;
            g_y_l[(size_t)tok*DI + d] = __float2half_rn(v - __half2float(h));
        }
    }
}

// ---------------- launch ----------------
extern "C" void kernel_launch(void* const* d_in, const int* in_sizes, int n_in,
                              void* d_out, int out_size) {
    const int*   ids      = (const int*)  d_in[0];
    const float* emb      = (const float*)d_in[1];
    const float* norm_f_w = (const float*)d_in[2];
    const float* W_in_l   = (const float*)d_in[3];
    const float* W_in_r   = (const float*)d_in[4];
    const float* conv_w   = (const float*)d_in[5];
    const float* conv_b   = (const float*)d_in[6];
    const float* W_x      = (const float*)d_in[7];
    const float* W_dt     = (const float*)d_in[8];
    const float* A_log    = (const float*)d_in[9];
    const float* Dp       = (const float*)d_in[10];
    const float* W_out    = (const float*)d_in[11];
    const float* norm_w   = (const float*)d_in[12];
    float* out = (float*)d_out;

    float *p_x, *p_ir, *p_u, *p_xdbl, *p_dlt;
    cudaGetSymbolAddress((void**)&p_x,    g_x);
    cudaGetSymbolAddress((void**)&p_ir,   g_ir);
    cudaGetSymbolAddress((void**)&p_u,    g_u);
    cudaGetSymbolAddress((void**)&p_xdbl, g_xdbl);
    cudaGetSymbolAddress((void**)&p_dlt,  g_dlt);

    __half *p_ef, *p_xnh, *p_xnl, *p_uh, *p_ul, *p_xdh, *p_xdl, *p_yh, *p_yl, *p_wf;
    cudaGetSymbolAddress((void**)&p_ef,  g_emb_f);
    cudaGetSymbolAddress((void**)&p_xnh, g_xn_h);
    cudaGetSymbolAddress((void**)&p_xnl, g_xn_l);
    cudaGetSymbolAddress((void**)&p_uh,  g_u_h);
    cudaGetSymbolAddress((void**)&p_ul,  g_u_l);
    cudaGetSymbolAddress((void**)&p_xdh, g_xd_h);
    cudaGetSymbolAddress((void**)&p_xdl, g_xd_l);
    cudaGetSymbolAddress((void**)&p_yh,  g_y_h);
    cudaGetSymbolAddress((void**)&p_yl,  g_y_l);
    cudaGetSymbolAddress((void**)&p_wf,  g_w_f);

    cudaFuncSetAttribute(k_mma<EPI_NONE>,     cudaFuncAttributeMaxDynamicSharedMemorySize, SMEM_DYN);
    cudaFuncSetAttribute(k_mma<EPI_SOFTPLUS>, cudaFuncAttributeMaxDynamicSharedMemorySize, SMEM_DYN);
    cudaFuncSetAttribute(k_mma<EPI_RESADD>,   cudaFuncAttributeMaxDynamicSharedMemorySize, SMEM_DYN);

    k_embed<<<TT, 256>>>(ids, emb);                               // launch 0
    k_cvt<<<(VOCAB*DM/8 + 255)/256, 256>>>(emb, p_ef, VOCAB*DM);  // launch 1

    for (int i = 0; i < NLAYER; i++) {
        const float* Wl  = W_in_l + (size_t)i*DI*DM;
        const float* Wr  = W_in_r + (size_t)i*DI*DM;
        const float* cw  = conv_w + (size_t)i*DI*DC;
        const float* cb  = conv_b + (size_t)i*DI;
        const float* Wx  = W_x    + (size_t)i*(DR+2*DS)*DI;
        const float* Wdt = W_dt   + (size_t)i*DI*DR;
        const float* Al  = A_log  + (size_t)i*DI*DS;
        const float* Dpi = Dp     + (size_t)i*DI;
        const float* Wo  = W_out  + (size_t)i*DM*DI;
        const float* nw  = norm_w + (size_t)i*DM;

        k_rmsnorm<<<TT, 256>>>(p_x, nw, p_xnh, p_xnl);            // launch 2 (i=0)

        // fused in-proj: [xi|res] = xn @ [Wl;Wr]^T   (2048 x 4096, K=1024)
        k_cvt<<<(DI*DM/8 + 255)/256, 256>>>(Wl, p_wf, DI*DM);             // launch 3
        k_cvt<<<(DI*DM/8 + 255)/256, 256>>>(Wr, p_wf + DI*DM, DI*DM);     // launch 4
        k_mma<EPI_NONE><<<dim3(TT/128, 2*DI/128), 256, SMEM_DYN>>>(       // launch 5 <- ncu
            p_xnh, p_xnl, DM, p_wf, DM, p_ir, 2*DI, TT, 2*DI, DM, nullptr);

        k_conv_silu<<<(TT*DI + 255)/256, 256>>>(cw, cb);

        // x_dbl = u @ Wx^T  (2048 x 96, K=2048)
        k_cvt<<<(96*DI/8 + 255)/256, 256>>>(Wx, p_wf, 96*DI);
        k_mma<EPI_NONE><<<dim3(TT/128, 1), 256, SMEM_DYN>>>(
            p_uh, p_ul, DI, p_wf, DI, p_xdbl, 96, TT, 96, DI, nullptr);

        k_split<<<(TT*96/4 + 255)/256, 256>>>(p_xdbl, p_xdh, p_xdl, TT*96);

        // delta = softplus(x_dbl[:, :64] @ Wdt^T)  (2048 x 2048, K=64)
        k_cvt<<<(DI*DR/8 + 255)/256, 256>>>(Wdt, p_wf, DI*DR);
        k_mma<EPI_SOFTPLUS><<<dim3(TT/128, DI/128), 256, SMEM_DYN>>>(
            p_xdh, p_xdl, 96, p_wf, DR, p_dlt, DI, TT, DI, DR, nullptr);

        k_scan<<<(BB*DI)/16, 256>>>(Al, Dpi);

        // x = y @ Wo^T + x  (2048 x 1024, K=2048)
        k_cvt<<<(DM*DI/8 + 255)/256, 256>>>(Wo, p_wf, DM*DI);
        k_mma<EPI_RESADD><<<dim3(TT/128, DM/128), 256, SMEM_DYN>>>(
            p_yh, p_yl, DI, p_wf, DI, p_x, DM, TT, DM, DI, p_x);
    }

    // final norm + logits (2048 x 32000, K=1024)
    k_rmsnorm<<<TT, 256>>>(p_x, norm_f_w, p_xnh, p_xnl);
    k_mma<EPI_NONE><<<dim3(TT/128, VOCAB/128), 256, SMEM_DYN>>>(
        p_xnh, p_xnl, DM, p_ef, DM, out, VOCAB, TT, VOCAB, DM, nullptr);
}

// round 8
// speedup vs baseline: 1.3725x; 1.2818x over previous
#include <cuda_runtime.h>
#include <cuda_fp16.h>
#include <cuda_bf16.h>
#include <cstdint>

// ---------------- problem constants ----------------
#define DM     1024
#define NLAYER 2
#define VOCAB  32000
#define DS     16
#define DI     2048
#define DR     64
#define DC     4
#define BB     2
#define LL     1024
#define TT     (BB*LL)

// ---------------- device scratch (fp32) ----------------
__device__ float g_x   [TT*DM];
__device__ float g_ir  [TT*2*DI];    // [xi(2048) | res(2048)] fused in-proj output
__device__ float g_u   [TT*DI];
__device__ float g_xdbl[TT*96];
__device__ float g_dlt [TT*DI];

// ---------------- fp16 buffers (plain, 1-term) ----------------
__device__ __half g_emb_f[VOCAB*DM];
__device__ __half g_xn_f [TT*DM];
__device__ __half g_u_f  [TT*DI];
__device__ __half g_xd_f [TT*96];
__device__ __half g_y_f  [TT*DI];
__device__ __half g_w_f  [2*DI*DM];   // room for Wl+Wr fused

// ---------------- helpers ----------------
static __device__ __forceinline__ uint32_t s2u(const void* p) {
    uint32_t a;
    asm("{ .reg .u64 t; cvta.to.shared.u64 t, %1; cvt.u32.u64 %0, t; }" : "=r"(a) : "l"(p));
    return a;
}
static __device__ __forceinline__ void cp16(uint32_t s, const void* g, bool pred) {
    int sz = pred ? 16 : 0;
    asm volatile("cp.async.cg.shared.global [%0], [%1], 16, %2;" :: "r"(s), "l"(g), "r"(sz));
}
#define CP_COMMIT() asm volatile("cp.async.commit_group;" ::: "memory")
#define CP_WAIT2()  asm volatile("cp.async.wait_group 2;"  ::: "memory")

#define LDSM4(r, addr) asm volatile( \
    "ldmatrix.sync.aligned.m8n8.x4.shared.b16 {%0,%1,%2,%3}, [%4];" \
    : "=r"((r)[0]),"=r"((r)[1]),"=r"((r)[2]),"=r"((r)[3]) : "r"(addr))
#define MMA(d, a, b) asm volatile( \
    "mma.sync.aligned.m16n8k16.row.col.f32.f16.f16.f32 " \
    "{%0,%1,%2,%3},{%4,%5,%6,%7},{%8,%9},{%0,%1,%2,%3};" \
    : "+f"((d)[0]),"+f"((d)[1]),"+f"((d)[2]),"+f"((d)[3]) \
    : "r"((a)[0]),"r"((a)[1]),"r"((a)[2]),"r"((a)[3]),"r"((b)[0]),"r"((b)[1]))

// ---------------- embed ----------------
__global__ void k_embed(const int* __restrict__ ids, const float* __restrict__ emb) {
    int t = blockIdx.x;
    int id = ids[t];
    for (int c = threadIdx.x; c < DM; c += blockDim.x)
        g_x[t*DM + c] = emb[id*DM + c];
}

// ---------------- rmsnorm -> fp16 ----------------
__global__ void k_rmsnorm(const float* __restrict__ x, const float* __restrict__ w,
                          __half* __restrict__ of) {
    int t = blockIdx.x;
    const float* xr = x + t*DM;
    float s = 0.f;
    for (int c = threadIdx.x; c < DM; c += blockDim.x) { float v = xr[c]; s += v*v; }
    for (int o = 16; o > 0; o >>= 1) s += __shfl_xor_sync(0xffffffffu, s, o);
    __shared__ float red[8];
    int wid = threadIdx.x >> 5, lid = threadIdx.x & 31;
    if (lid == 0) red[wid] = s;
    __syncthreads();
    if (wid == 0) {
        float v = (lid < (blockDim.x >> 5)) ? red[lid] : 0.f;
        for (int o = 4; o > 0; o >>= 1) v += __shfl_xor_sync(0xffffffffu, v, o);
        if (lid == 0) red[0] = v;
    }
    __syncthreads();
    float scale = rsqrtf(red[0] / (float)DM + 1e-5f);
    for (int c = threadIdx.x; c < DM; c += blockDim.x)
        of[t*DM + c] = __float2half_rn(xr[c] * scale * w[c]);
}

// ---------------- fp32 -> fp16 plain convert ----------------
__global__ void k_cvt(const float* __restrict__ x, __half* __restrict__ o, int n) {
    int i = (blockIdx.x * blockDim.x + threadIdx.x) * 8;
    if (i >= n) return;
    float4 a = *reinterpret_cast<const float4*>(x + i);
    float4 b = *reinterpret_cast<const float4*>(x + i + 4);
    __half2 p0, p1, p2, p3;
    p0.x = __float2half_rn(a.x); p0.y = __float2half_rn(a.y);
    p1.x = __float2half_rn(a.z); p1.y = __float2half_rn(a.w);
    p2.x = __float2half_rn(b.x); p2.y = __float2half_rn(b.y);
    p3.x = __float2half_rn(b.z); p3.y = __float2half_rn(b.w);
    uint4 pk;
    pk.x = *reinterpret_cast<uint32_t*>(&p0);
    pk.y = *reinterpret_cast<uint32_t*>(&p1);
    pk.z = *reinterpret_cast<uint32_t*>(&p2);
    pk.w = *reinterpret_cast<uint32_t*>(&p3);
    *reinterpret_cast<uint4*>(o + i) = pk;
}

// two sources -> one contiguous fp16 buffer (Wl | Wr)
__global__ void k_cvt2(const float* __restrict__ x0, const float* __restrict__ x1,
                       __half* __restrict__ o, int n_each) {
    int i = (blockIdx.x * blockDim.x + threadIdx.x) * 8;
    if (i >= 2*n_each) return;
    const float* src = (i < n_each) ? (x0 + i) : (x1 + i - n_each);
    float4 a = *reinterpret_cast<const float4*>(src);
    float4 b = *reinterpret_cast<const float4*>(src + 4);
    __half2 p0, p1, p2, p3;
    p0.x = __float2half_rn(a.x); p0.y = __float2half_rn(a.y);
    p1.x = __float2half_rn(a.z); p1.y = __float2half_rn(a.w);
    p2.x = __float2half_rn(b.x); p2.y = __float2half_rn(b.y);
    p3.x = __float2half_rn(b.z); p3.y = __float2half_rn(b.w);
    uint4 pk;
    pk.x = *reinterpret_cast<uint32_t*>(&p0);
    pk.y = *reinterpret_cast<uint32_t*>(&p1);
    pk.z = *reinterpret_cast<uint32_t*>(&p2);
    pk.w = *reinterpret_cast<uint32_t*>(&p3);
    *reinterpret_cast<uint4*>(o + i) = pk;
}

// ---------------- HMMA GEMM: C[M,N] = A[M,K] @ B[N,K]^T, plain fp16 ----------------
#define EPI_NONE     0
#define EPI_SOFTPLUS 1
#define EPI_RESADD   2

#define TILE_B   8192          // 128 rows x 64 bytes (BK=32 fp16)
#define OFF_A    0
#define OFF_B    (TILE_B)
#define STAGE_B  (2*TILE_B)    // 16 KB
#define NSTAGE   4
#define SMEM_DYN (NSTAGE*STAGE_B)   // 64 KB

__device__ __forceinline__ void load_stage(uint32_t sbase,
        const __half* __restrict__ A, int lda, int m0,
        const __half* __restrict__ Bf, int ldb, int n0, int N, int k0, int tid) {
    #pragma unroll
    for (int it = 0; it < 2; it++) {
        int i = tid + it*256;
        int r = i >> 2;
        int cby = (i & 3) * 16;
        uint32_t off = r*64 + (cby ^ (((r >> 1) & 3) << 4));
        size_t ga = (size_t)(m0 + r)*lda + k0 + (i & 3)*8;
        cp16(sbase + OFF_A + off, A + ga, true);
        bool bp = (n0 + r) < N;
        size_t gb = (size_t)(bp ? (n0 + r) : 0)*ldb + k0 + (i & 3)*8;
        cp16(sbase + OFF_B + off, Bf + gb, bp);
    }
}

template<int EPI>
__global__ void __launch_bounds__(256, 2) k_mma(
        const __half* __restrict__ A, int lda,
        const __half* __restrict__ Bf, int ldb,
        float* __restrict__ C, int ldc, int M, int N, int K,
        const float* __restrict__ R) {
    extern __shared__ __align__(1024) char smem[];
    const uint32_t sb = s2u(smem);
    const int tid = threadIdx.x, lane = tid & 31, wid = tid >> 5;
    const int wm = wid >> 2, wn = wid & 3;       // 2 x 4 warp grid, 64x32 per warp
    const int m0 = blockIdx.x * 128, n0 = blockIdx.y * 128;

    float acc[4][4][4];
    #pragma unroll
    for (int a = 0; a < 4; a++)
        #pragma unroll
        for (int b = 0; b < 4; b++)
            #pragma unroll
            for (int c = 0; c < 4; c++) acc[a][b][c] = 0.f;

    const int NC = K / 32;
    #pragma unroll
    for (int p = 0; p < 3; p++) {
        if (p < NC)
            load_stage(sb + p*STAGE_B, A, lda, m0, Bf, ldb, n0, N, p*32, tid);
        CP_COMMIT();
    }

    const int arow = lane & 15;
    const int acb  = ((lane >> 4) & 1) * 16;
    const int brow = lane & 7;
    const int bnt  = (lane >> 4) & 1;
    const int bkh  = (lane >> 3) & 1;

    int stage = 0;
    for (int c = 0; c < NC; c++) {
        CP_WAIT2();
        __syncthreads();
        if (c + 3 < NC) {
            int s3 = stage + 3; if (s3 >= NSTAGE) s3 -= NSTAGE;
            load_stage(sb + s3*STAGE_B, A, lda, m0, Bf, ldb, n0, N, (c + 3)*32, tid);
        }
        CP_COMMIT();

        uint32_t st = sb + stage*STAGE_B;
        #pragma unroll
        for (int kk = 0; kk < 2; kk++) {
            uint32_t bf[4][2], af[4][4];
            #pragma unroll
            for (int p = 0; p < 2; p++) {
                int r = wn*32 + (p*2 + bnt)*8 + brow;
                uint32_t off = r*64 + (((kk*2 + bkh)*16) ^ (((r >> 1) & 3) << 4));
                uint32_t t[4];
                LDSM4(t, st + OFF_B + off);
                bf[2*p][0] = t[0]; bf[2*p][1] = t[1];
                bf[2*p+1][0] = t[2]; bf[2*p+1][1] = t[3];
            }
            #pragma unroll
            for (int mt = 0; mt < 4; mt++) {
                int r = wm*64 + mt*16 + arow;
                uint32_t off = r*64 + ((kk*32 + acb) ^ (((r >> 1) & 3) << 4));
                LDSM4(af[mt], st + OFF_A + off);
            }
            #pragma unroll
            for (int mt = 0; mt < 4; mt++)
                #pragma unroll
                for (int nt = 0; nt < 4; nt++)
                    MMA(acc[mt][nt], af[mt], bf[nt]);
        }
        stage++; if (stage >= NSTAGE) stage = 0;
    }

    // epilogue
    #pragma unroll
    for (int mt = 0; mt < 4; mt++) {
        #pragma unroll
        for (int nt = 0; nt < 4; nt++) {
            int row = m0 + wm*64 + mt*16 + (lane >> 2);
            int col = n0 + wn*32 + nt*8 + (lane & 3)*2;
            if (col < N) {
                #pragma unroll
                for (int h = 0; h < 2; h++) {
                    int rr = row + h*8;
                    float v0 = acc[mt][nt][2*h + 0];
                    float v1 = acc[mt][nt][2*h + 1];
                    if (EPI == EPI_SOFTPLUS) {
                        v0 = (v0 > 20.f) ? v0 : log1pf(expf(v0));
                        v1 = (v1 > 20.f) ? v1 : log1pf(expf(v1));
                    }
                    if (EPI == EPI_RESADD) {
                        v0 += R[(size_t)rr*ldc + col];
                        v1 += R[(size_t)rr*ldc + col + 1];
                    }
                    *reinterpret_cast<float2*>(&C[(size_t)rr*ldc + col]) = make_float2(v0, v1);
                }
            }
        }
    }
}

// ---------------- depthwise causal conv + bias + SiLU ----------------
__global__ void k_conv_silu(const float* __restrict__ cw, const float* __restrict__ cb) {
    int idx = blockIdx.x * blockDim.x + threadIdx.x;
    if (idx >= TT*DI) return;
    int d = idx % DI;
    int l = (idx / DI) % LL;
    int b = idx / (DI*LL);
    float acc = cb[d];
    #pragma unroll
    for (int j = 0; j < DC; j++) {
        int ll = l - (DC-1) + j;
        if (ll >= 0) acc = fmaf(cw[d*DC + j], g_ir[((size_t)b*LL + ll)*(2*DI) + d], acc);
    }
    float s = acc / (1.f + __expf(-acc));
    g_u[idx] = s;
    g_u_f[idx] = __float2half_rn(s);
}

// ---------------- selective scan + gate ----------------
__global__ void k_scan(const float* __restrict__ A_log, const float* __restrict__ Dp) {
    int lane = threadIdx.x & 15;
    int grp  = threadIdx.x >> 4;
    int ch   = blockIdx.x * 16 + grp;
    int b = ch / DI, d = ch % DI;

    float An = -__expf(A_log[d*DS + lane]);
    float Dv = Dp[d];
    float xs = 0.f;

    for (int l = 0; l < LL; l++) {
        int tok = b*LL + l;
        float dlt = g_dlt[(size_t)tok*DI + d];
        float uu  = g_u  [(size_t)tok*DI + d];
        float Bn  = g_xdbl[(size_t)tok*96 + 64 + lane];
        float Cn  = g_xdbl[(size_t)tok*96 + 80 + lane];
        float dA  = __expf(dlt * An);
        xs = fmaf(dA, xs, dlt * uu * Bn);
        float yv = xs * Cn;
        yv += __shfl_xor_sync(0xffffffffu, yv, 8);
        yv += __shfl_xor_sync(0xffffffffu, yv, 4);
        yv += __shfl_xor_sync(0xffffffffu, yv, 2);
        yv += __shfl_xor_sync(0xffffffffu, yv, 1);
        if (lane == 0) {
            float r = g_ir[(size_t)tok*(2*DI) + DI + d];
            float gate = r / (1.f + __expf(-r));
            g_y_f[(size_t)tok*DI + d] = __float2half_rn((yv + uu * Dv) * gate);
        }
    }
}

// ---------------- launch ----------------
extern "C" void kernel_launch(void* const* d_in, const int* in_sizes, int n_in,
                              void* d_out, int out_size) {
    const int*   ids      = (const int*)  d_in[0];
    const float* emb      = (const float*)d_in[1];
    const float* norm_f_w = (const float*)d_in[2];
    const float* W_in_l   = (const float*)d_in[3];
    const float* W_in_r   = (const float*)d_in[4];
    const float* conv_w   = (const float*)d_in[5];
    const float* conv_b   = (const float*)d_in[6];
    const float* W_x      = (const float*)d_in[7];
    const float* W_dt     = (const float*)d_in[8];
    const float* A_log    = (const float*)d_in[9];
    const float* Dp       = (const float*)d_in[10];
    const float* W_out    = (const float*)d_in[11];
    const float* norm_w   = (const float*)d_in[12];
    float* out = (float*)d_out;

    float *p_x, *p_ir, *p_u, *p_xdbl, *p_dlt;
    cudaGetSymbolAddress((void**)&p_x,    g_x);
    cudaGetSymbolAddress((void**)&p_ir,   g_ir);
    cudaGetSymbolAddress((void**)&p_u,    g_u);
    cudaGetSymbolAddress((void**)&p_xdbl, g_xdbl);
    cudaGetSymbolAddress((void**)&p_dlt,  g_dlt);

    __half *p_ef, *p_xnf, *p_uf, *p_xdf, *p_yf, *p_wf;
    cudaGetSymbolAddress((void**)&p_ef,  g_emb_f);
    cudaGetSymbolAddress((void**)&p_xnf, g_xn_f);
    cudaGetSymbolAddress((void**)&p_uf,  g_u_f);
    cudaGetSymbolAddress((void**)&p_xdf, g_xd_f);
    cudaGetSymbolAddress((void**)&p_yf,  g_y_f);
    cudaGetSymbolAddress((void**)&p_wf,  g_w_f);

    cudaFuncSetAttribute(k_mma<EPI_NONE>,     cudaFuncAttributeMaxDynamicSharedMemorySize, SMEM_DYN);
    cudaFuncSetAttribute(k_mma<EPI_SOFTPLUS>, cudaFuncAttributeMaxDynamicSharedMemorySize, SMEM_DYN);
    cudaFuncSetAttribute(k_mma<EPI_RESADD>,   cudaFuncAttributeMaxDynamicSharedMemorySize, SMEM_DYN);

    bool first = true;
    k_embed<<<TT, 256>>>(ids, emb);                               // launch 0

    for (int i = 0; i < NLAYER; i++) {
        const float* Wl  = W_in_l + (size_t)i*DI*DM;
        const float* Wr  = W_in_r + (size_t)i*DI*DM;
        const float* cw  = conv_w + (size_t)i*DI*DC;
        const float* cb  = conv_b + (size_t)i*DI;
        const float* Wx  = W_x    + (size_t)i*(DR+2*DS)*DI;
        const float* Wdt = W_dt   + (size_t)i*DI*DR;
        const float* Al  = A_log  + (size_t)i*DI*DS;
        const float* Dpi = Dp     + (size_t)i*DI;
        const float* Wo  = W_out  + (size_t)i*DM*DI;
        const float* nw  = norm_w + (size_t)i*DM;

        // launch 1 (i=0): fused Wl|Wr convert
        k_cvt2<<<(2*DI*DM/8 + 255)/256, 256>>>(Wl, Wr, p_wf, DI*DM);
        // launch 2 (i=0): rmsnorm
        k_rmsnorm<<<TT, 256>>>(p_x, nw, p_xnf);
        // launch 3 (i=0): fused in-proj GEMM  <-- ncu capture target
        k_mma<EPI_NONE><<<dim3(TT/128, 2*DI/128), 256, SMEM_DYN>>>(
            p_xnf, DM, p_wf, DM, p_ir, 2*DI, TT, 2*DI, DM, nullptr);
        (void)first; first = false;

        k_conv_silu<<<(TT*DI + 255)/256, 256>>>(cw, cb);

        // x_dbl = u @ Wx^T  (2048 x 96, K=2048)
        k_cvt<<<(96*DI/8 + 255)/256, 256>>>(Wx, p_wf, 96*DI);
        k_mma<EPI_NONE><<<dim3(TT/128, 1), 256, SMEM_DYN>>>(
            p_uf, DI, p_wf, DI, p_xdbl, 96, TT, 96, DI, nullptr);

        k_cvt<<<(TT*96/8 + 255)/256, 256>>>(p_xdbl, p_xdf, TT*96);

        // delta = softplus(x_dbl[:, :64] @ Wdt^T)  (2048 x 2048, K=64)
        k_cvt<<<(DI*DR/8 + 255)/256, 256>>>(Wdt, p_wf, DI*DR);
        k_mma<EPI_SOFTPLUS><<<dim3(TT/128, DI/128), 256, SMEM_DYN>>>(
            p_xdf, 96, p_wf, DR, p_dlt, DI, TT, DI, DR, nullptr);

        k_scan<<<(BB*DI)/16, 256>>>(Al, Dpi);

        // x = y @ Wo^T + x  (2048 x 1024, K=2048)
        k_cvt<<<(DM*DI/8 + 255)/256, 256>>>(Wo, p_wf, DM*DI);
        k_mma<EPI_RESADD><<<dim3(TT/128, DM/128), 256, SMEM_DYN>>>(
            p_yf, DI, p_wf, DI, p_x, DM, TT, DM, DI, p_x);
    }

    // final norm + logits (2048 x 32000, K=1024)
    k_cvt<<<(VOCAB*DM/8 + 255)/256, 256>>>(emb, p_ef, VOCAB*DM);
    k_rmsnorm<<<TT, 256>>>(p_x, norm_f_w, p_xnf);
    k_mma<EPI_NONE><<<dim3(TT/128, VOCAB/128), 256, SMEM_DYN>>>(
        p_xnf, DM, p_ef, DM, out, VOCAB, TT, VOCAB, DM, nullptr);
}

// round 9
// speedup vs baseline: 1.7026x; 1.2405x over previous
#include <cuda_runtime.h>
#include <cuda_fp16.h>
#include <cuda_bf16.h>
#include <cstdint>

// ---------------- problem constants ----------------
#define DM     1024
#define NLAYER 2
#define VOCAB  32000
#define DS     16
#define DI     2048
#define DR     64
#define DC     4
#define BB     2
#define LL     1024
#define TT     (BB*LL)

// ---------------- device scratch (fp32) ----------------
__device__ float g_x   [TT*DM];
__device__ float g_ir  [TT*2*DI];    // [xi(2048) | res(2048)] fused in-proj output
__device__ float g_u   [TT*DI];
__device__ float g_xdbl[TT*96];
__device__ float g_dlt [TT*DI];
__device__ float g_part[2*TT*DM];    // split-K partials (also covers 8*TT*96)

// ---------------- fp16 buffers ----------------
__device__ __half g_emb_f[VOCAB*DM];
__device__ __half g_xn_f [TT*DM];
__device__ __half g_u_f  [TT*DI];
__device__ __half g_xd_f [TT*96];
__device__ __half g_y_f  [TT*DI];
__device__ __half g_w_f  [2*DI*DM];

// ---------------- helpers ----------------
static __device__ __forceinline__ uint32_t s2u(const void* p) {
    uint32_t a;
    asm("{ .reg .u64 t; cvta.to.shared.u64 t, %1; cvt.u32.u64 %0, t; }" : "=r"(a) : "l"(p));
    return a;
}
static __device__ __forceinline__ void cp16(uint32_t s, const void* g, bool pred) {
    int sz = pred ? 16 : 0;
    asm volatile("cp.async.cg.shared.global [%0], [%1], 16, %2;" :: "r"(s), "l"(g), "r"(sz));
}
#define CP_COMMIT() asm volatile("cp.async.commit_group;" ::: "memory")
#define CP_WAIT2()  asm volatile("cp.async.wait_group 2;"  ::: "memory")

#define LDSM4(r, addr) asm volatile( \
    "ldmatrix.sync.aligned.m8n8.x4.shared.b16 {%0,%1,%2,%3}, [%4];" \
    : "=r"((r)[0]),"=r"((r)[1]),"=r"((r)[2]),"=r"((r)[3]) : "r"(addr))
#define MMA(d, a, b) asm volatile( \
    "mma.sync.aligned.m16n8k16.row.col.f32.f16.f16.f32 " \
    "{%0,%1,%2,%3},{%4,%5,%6,%7},{%8,%9},{%0,%1,%2,%3};" \
    : "+f"((d)[0]),"+f"((d)[1]),"+f"((d)[2]),"+f"((d)[3]) \
    : "r"((a)[0]),"r"((a)[1]),"r"((a)[2]),"r"((a)[3]),"r"((b)[0]),"r"((b)[1]))

// ---------------- embed ----------------
__global__ void k_embed(const int* __restrict__ ids, const float* __restrict__ emb) {
    int t = blockIdx.x;
    int id = ids[t];
    for (int c = threadIdx.x; c < DM; c += blockDim.x)
        g_x[t*DM + c] = emb[id*DM + c];
}

// ---------------- rmsnorm -> fp16 ----------------
__global__ void k_rmsnorm(const float* __restrict__ x, const float* __restrict__ w,
                          __half* __restrict__ of) {
    int t = blockIdx.x;
    const float* xr = x + t*DM;
    float s = 0.f;
    for (int c = threadIdx.x; c < DM; c += blockDim.x) { float v = xr[c]; s += v*v; }
    for (int o = 16; o > 0; o >>= 1) s += __shfl_xor_sync(0xffffffffu, s, o);
    __shared__ float red[8];
    int wid = threadIdx.x >> 5, lid = threadIdx.x & 31;
    if (lid == 0) red[wid] = s;
    __syncthreads();
    if (wid == 0) {
        float v = (lid < (blockDim.x >> 5)) ? red[lid] : 0.f;
        for (int o = 4; o > 0; o >>= 1) v += __shfl_xor_sync(0xffffffffu, v, o);
        if (lid == 0) red[0] = v;
    }
    __syncthreads();
    float scale = rsqrtf(red[0] / (float)DM + 1e-5f);
    for (int c = threadIdx.x; c < DM; c += blockDim.x)
        of[t*DM + c] = __float2half_rn(xr[c] * scale * w[c]);
}

// ---------------- fp32 -> fp16 convert ----------------
__global__ void k_cvt(const float* __restrict__ x, __half* __restrict__ o, int n) {
    int i = (blockIdx.x * blockDim.x + threadIdx.x) * 8;
    if (i >= n) return;
    float4 a = *reinterpret_cast<const float4*>(x + i);
    float4 b = *reinterpret_cast<const float4*>(x + i + 4);
    __half2 p0, p1, p2, p3;
    p0.x = __float2half_rn(a.x); p0.y = __float2half_rn(a.y);
    p1.x = __float2half_rn(a.z); p1.y = __float2half_rn(a.w);
    p2.x = __float2half_rn(b.x); p2.y = __float2half_rn(b.y);
    p3.x = __float2half_rn(b.z); p3.y = __float2half_rn(b.w);
    uint4 pk;
    pk.x = *reinterpret_cast<uint32_t*>(&p0);
    pk.y = *reinterpret_cast<uint32_t*>(&p1);
    pk.z = *reinterpret_cast<uint32_t*>(&p2);
    pk.w = *reinterpret_cast<uint32_t*>(&p3);
    *reinterpret_cast<uint4*>(o + i) = pk;
}

// two sources -> one contiguous fp16 buffer (Wl | Wr)
__global__ void k_cvt2(const float* __restrict__ x0, const float* __restrict__ x1,
                       __half* __restrict__ o, int n_each) {
    int i = (blockIdx.x * blockDim.x + threadIdx.x) * 8;
    if (i >= 2*n_each) return;
    const float* src = (i < n_each) ? (x0 + i) : (x1 + i - n_each);
    float4 a = *reinterpret_cast<const float4*>(src);
    float4 b = *reinterpret_cast<const float4*>(src + 4);
    __half2 p0, p1, p2, p3;
    p0.x = __float2half_rn(a.x); p0.y = __float2half_rn(a.y);
    p1.x = __float2half_rn(a.z); p1.y = __float2half_rn(a.w);
    p2.x = __float2half_rn(b.x); p2.y = __float2half_rn(b.y);
    p3.x = __float2half_rn(b.z); p3.y = __float2half_rn(b.w);
    uint4 pk;
    pk.x = *reinterpret_cast<uint32_t*>(&p0);
    pk.y = *reinterpret_cast<uint32_t*>(&p1);
    pk.z = *reinterpret_cast<uint32_t*>(&p2);
    pk.w = *reinterpret_cast<uint32_t*>(&p3);
    *reinterpret_cast<uint4*>(o + i) = pk;
}

// ---------------- HMMA GEMM (split-K capable via blockIdx.z) ----------------
#define EPI_NONE     0
#define EPI_SOFTPLUS 1
#define EPI_RESADD   2

#define TILE_B   8192
#define OFF_A    0
#define OFF_B    (TILE_B)
#define STAGE_B  (2*TILE_B)
#define NSTAGE   4
#define SMEM_DYN (NSTAGE*STAGE_B)   // 64 KB

__device__ __forceinline__ void load_stage(uint32_t sbase,
        const __half* __restrict__ A, int lda, int m0,
        const __half* __restrict__ Bf, int ldb, int n0, int N, int k0, int tid) {
    #pragma unroll
    for (int it = 0; it < 2; it++) {
        int i = tid + it*256;
        int r = i >> 2;
        int cby = (i & 3) * 16;
        uint32_t off = r*64 + (cby ^ (((r >> 1) & 3) << 4));
        size_t ga = (size_t)(m0 + r)*lda + k0 + (i & 3)*8;
        cp16(sbase + OFF_A + off, A + ga, true);
        bool bp = (n0 + r) < N;
        size_t gb = (size_t)(bp ? (n0 + r) : 0)*ldb + k0 + (i & 3)*8;
        cp16(sbase + OFF_B + off, Bf + gb, bp);
    }
}

template<int EPI>
__global__ void __launch_bounds__(256, 2) k_mma(
        const __half* __restrict__ A, int lda,
        const __half* __restrict__ Bf, int ldb,
        float* __restrict__ C, int ldc, int M, int N, int Kslice,
        const float* __restrict__ R) {
    extern __shared__ __align__(1024) char smem[];
    const uint32_t sb = s2u(smem);
    const int tid = threadIdx.x, lane = tid & 31, wid = tid >> 5;
    const int wm = wid >> 2, wn = wid & 3;
    const int m0 = blockIdx.x * 128, n0 = blockIdx.y * 128;
    const int z = blockIdx.z;
    A  += (size_t)z * Kslice;
    Bf += (size_t)z * Kslice;
    C  += (size_t)z * M * ldc;

    float acc[4][4][4];
    #pragma unroll
    for (int a = 0; a < 4; a++)
        #pragma unroll
        for (int b = 0; b < 4; b++)
            #pragma unroll
            for (int c = 0; c < 4; c++) acc[a][b][c] = 0.f;

    const int NC = Kslice / 32;
    #pragma unroll
    for (int p = 0; p < 3; p++) {
        if (p < NC)
            load_stage(sb + p*STAGE_B, A, lda, m0, Bf, ldb, n0, N, p*32, tid);
        CP_COMMIT();
    }

    const int arow = lane & 15;
    const int acb  = ((lane >> 4) & 1) * 16;
    const int brow = lane & 7;
    const int bnt  = (lane >> 4) & 1;
    const int bkh  = (lane >> 3) & 1;

    int stage = 0;
    for (int c = 0; c < NC; c++) {
        CP_WAIT2();
        __syncthreads();
        if (c + 3 < NC) {
            int s3 = stage + 3; if (s3 >= NSTAGE) s3 -= NSTAGE;
            load_stage(sb + s3*STAGE_B, A, lda, m0, Bf, ldb, n0, N, (c + 3)*32, tid);
        }
        CP_COMMIT();

        uint32_t st = sb + stage*STAGE_B;
        #pragma unroll
        for (int kk = 0; kk < 2; kk++) {
            uint32_t bf[4][2], af[4][4];
            #pragma unroll
            for (int p = 0; p < 2; p++) {
                int r = wn*32 + (p*2 + bnt)*8 + brow;
                uint32_t off = r*64 + (((kk*2 + bkh)*16) ^ (((r >> 1) & 3) << 4));
                uint32_t t[4];
                LDSM4(t, st + OFF_B + off);
                bf[2*p][0] = t[0]; bf[2*p][1] = t[1];
                bf[2*p+1][0] = t[2]; bf[2*p+1][1] = t[3];
            }
            #pragma unroll
            for (int mt = 0; mt < 4; mt++) {
                int r = wm*64 + mt*16 + arow;
                uint32_t off = r*64 + ((kk*32 + acb) ^ (((r >> 1) & 3) << 4));
                LDSM4(af[mt], st + OFF_A + off);
            }
            #pragma unroll
            for (int mt = 0; mt < 4; mt++)
                #pragma unroll
                for (int nt = 0; nt < 4; nt++)
                    MMA(acc[mt][nt], af[mt], bf[nt]);
        }
        stage++; if (stage >= NSTAGE) stage = 0;
    }

    #pragma unroll
    for (int mt = 0; mt < 4; mt++) {
        #pragma unroll
        for (int nt = 0; nt < 4; nt++) {
            int row = m0 + wm*64 + mt*16 + (lane >> 2);
            int col = n0 + wn*32 + nt*8 + (lane & 3)*2;
            if (col < N) {
                #pragma unroll
                for (int h = 0; h < 2; h++) {
                    int rr = row + h*8;
                    float v0 = acc[mt][nt][2*h + 0];
                    float v1 = acc[mt][nt][2*h + 1];
                    if (EPI == EPI_SOFTPLUS) {
                        v0 = (v0 > 20.f) ? v0 : log1pf(expf(v0));
                        v1 = (v1 > 20.f) ? v1 : log1pf(expf(v1));
                    }
                    if (EPI == EPI_RESADD) {
                        v0 += R[(size_t)rr*ldc + col];
                        v1 += R[(size_t)rr*ldc + col + 1];
                    }
                    *reinterpret_cast<float2*>(&C[(size_t)rr*ldc + col]) = make_float2(v0, v1);
                }
            }
        }
    }
}

// ---------------- split-K reducers ----------------
// x_dbl: sum 8 partials -> fp32 + fp16
__global__ void k_redx(const float* __restrict__ part) {
    int i = blockIdx.x * blockDim.x + threadIdx.x;
    if (i >= TT*96) return;
    float s = 0.f;
    #pragma unroll
    for (int z = 0; z < 8; z++) s += part[(size_t)z*TT*96 + i];
    g_xdbl[i] = s;
    g_xd_f[i] = __float2half_rn(s);
}
// out-proj: sum 2 partials + residual -> g_x
__global__ void k_redadd(const float* __restrict__ part) {
    int i = blockIdx.x * blockDim.x + threadIdx.x;
    if (i >= TT*DM) return;
    g_x[i] = part[i] + part[(size_t)TT*DM + i] + g_x[i];
}

// ---------------- depthwise causal conv + bias + SiLU ----------------
__global__ void k_conv_silu(const float* __restrict__ cw, const float* __restrict__ cb) {
    int idx = blockIdx.x * blockDim.x + threadIdx.x;
    if (idx >= TT*DI) return;
    int d = idx % DI;
    int l = (idx / DI) % LL;
    int b = idx / (DI*LL);
    float acc = cb[d];
    #pragma unroll
    for (int j = 0; j < DC; j++) {
        int ll = l - (DC-1) + j;
        if (ll >= 0) acc = fmaf(cw[d*DC + j], g_ir[((size_t)b*LL + ll)*(2*DI) + d], acc);
    }
    float s = acc / (1.f + __expf(-acc));
    g_u[idx] = s;
    g_u_f[idx] = __float2half_rn(s);
}

// ---------------- selective scan + gate, 4-step batched ----------------
__global__ void k_scan(const float* __restrict__ A_log, const float* __restrict__ Dp) {
    int lane = threadIdx.x & 15;
    int grp  = threadIdx.x >> 4;
    int ch   = blockIdx.x * 16 + grp;
    int b = ch / DI, d = ch % DI;

    float An = -__expf(A_log[d*DS + lane]);
    float Dv = Dp[d];
    float xs = 0.f;

    for (int l0 = 0; l0 < LL; l0 += 4) {
        float dlt[4], uu[4], Bn[4], Cn[4], dA[4], yv[4];
        // batched loads (independent of recurrence)
        #pragma unroll
        for (int j = 0; j < 4; j++) {
            size_t tok = (size_t)(b*LL + l0 + j);
            dlt[j] = g_dlt[tok*DI + d];
            uu[j]  = g_u  [tok*DI + d];
            Bn[j]  = g_xdbl[tok*96 + 64 + lane];
            Cn[j]  = g_xdbl[tok*96 + 80 + lane];
        }
        // independent exps
        #pragma unroll
        for (int j = 0; j < 4; j++) dA[j] = __expf(dlt[j] * An);
        // recurrence chain: 4 dependent fmas only
        #pragma unroll
        for (int j = 0; j < 4; j++) {
            xs = fmaf(dA[j], xs, dlt[j] * uu[j] * Bn[j]);
            yv[j] = xs * Cn[j];
        }
        // interleaved reductions (4 independent chains)
        #pragma unroll
        for (int o = 8; o > 0; o >>= 1) {
            #pragma unroll
            for (int j = 0; j < 4; j++)
                yv[j] += __shfl_xor_sync(0xffffffffu, yv[j], o);
        }
        if (lane == 0) {
            #pragma unroll
            for (int j = 0; j < 4; j++) {
                size_t tok = (size_t)(b*LL + l0 + j);
                float r = g_ir[tok*(2*DI) + DI + d];
                float gate = r / (1.f + __expf(-r));
                g_y_f[tok*DI + d] = __float2half_rn((yv[j] + uu[j] * Dv) * gate);
            }
        }
    }
}

// ---------------- launch ----------------
extern "C" void kernel_launch(void* const* d_in, const int* in_sizes, int n_in,
                              void* d_out, int out_size) {
    const int*   ids      = (const int*)  d_in[0];
    const float* emb      = (const float*)d_in[1];
    const float* norm_f_w = (const float*)d_in[2];
    const float* W_in_l   = (const float*)d_in[3];
    const float* W_in_r   = (const float*)d_in[4];
    const float* conv_w   = (const float*)d_in[5];
    const float* conv_b   = (const float*)d_in[6];
    const float* W_x      = (const float*)d_in[7];
    const float* W_dt     = (const float*)d_in[8];
    const float* A_log    = (const float*)d_in[9];
    const float* Dp       = (const float*)d_in[10];
    const float* W_out    = (const float*)d_in[11];
    const float* norm_w   = (const float*)d_in[12];
    float* out = (float*)d_out;

    float *p_x, *p_ir, *p_u, *p_dlt, *p_part;
    cudaGetSymbolAddress((void**)&p_x,    g_x);
    cudaGetSymbolAddress((void**)&p_ir,   g_ir);
    cudaGetSymbolAddress((void**)&p_u,    g_u);
    cudaGetSymbolAddress((void**)&p_dlt,  g_dlt);
    cudaGetSymbolAddress((void**)&p_part, g_part);

    __half *p_ef, *p_xnf, *p_uf, *p_xdf, *p_yf, *p_wf;
    cudaGetSymbolAddress((void**)&p_ef,  g_emb_f);
    cudaGetSymbolAddress((void**)&p_xnf, g_xn_f);
    cudaGetSymbolAddress((void**)&p_uf,  g_u_f);
    cudaGetSymbolAddress((void**)&p_xdf, g_xd_f);
    cudaGetSymbolAddress((void**)&p_yf,  g_y_f);
    cudaGetSymbolAddress((void**)&p_wf,  g_w_f);

    cudaFuncSetAttribute(k_mma<EPI_NONE>,     cudaFuncAttributeMaxDynamicSharedMemorySize, SMEM_DYN);
    cudaFuncSetAttribute(k_mma<EPI_SOFTPLUS>, cudaFuncAttributeMaxDynamicSharedMemorySize, SMEM_DYN);
    cudaFuncSetAttribute(k_mma<EPI_RESADD>,   cudaFuncAttributeMaxDynamicSharedMemorySize, SMEM_DYN);

    k_embed<<<TT, 256>>>(ids, emb);                               // 0

    for (int i = 0; i < NLAYER; i++) {
        const float* Wl  = W_in_l + (size_t)i*DI*DM;
        const float* Wr  = W_in_r + (size_t)i*DI*DM;
        const float* cw  = conv_w + (size_t)i*DI*DC;
        const float* cb  = conv_b + (size_t)i*DI;
        const float* Wx  = W_x    + (size_t)i*(DR+2*DS)*DI;
        const float* Wdt = W_dt   + (size_t)i*DI*DR;
        const float* Al  = A_log  + (size_t)i*DI*DS;
        const float* Dpi = Dp     + (size_t)i*DI;
        const float* Wo  = W_out  + (size_t)i*DM*DI;
        const float* nw  = norm_w + (size_t)i*DM;

        k_cvt2<<<(2*DI*DM/8 + 255)/256, 256>>>(Wl, Wr, p_wf, DI*DM);   // 1 (i=0)
        k_rmsnorm<<<TT, 256>>>(p_x, nw, p_xnf);                        // 2 (i=0)
        // 3 (i=0): fused in-proj GEMM  <-- ncu capture
        k_mma<EPI_NONE><<<dim3(TT/128, 2*DI/128, 1), 256, SMEM_DYN>>>(
            p_xnf, DM, p_wf, DM, p_ir, 2*DI, TT, 2*DI, DM, nullptr);

        k_conv_silu<<<(TT*DI + 255)/256, 256>>>(cw, cb);

        // x_dbl = u @ Wx^T  (2048 x 96, K=2048) split-K x8
        k_cvt<<<(96*DI/8 + 255)/256, 256>>>(Wx, p_wf, 96*DI);
        k_mma<EPI_NONE><<<dim3(TT/128, 1, 8), 256, SMEM_DYN>>>(
            p_uf, DI, p_wf, DI, p_part, 96, TT, 96, DI/8, nullptr);
        k_redx<<<(TT*96 + 255)/256, 256>>>(p_part);

        // delta = softplus(x_dbl[:, :64] @ Wdt^T)  (2048 x 2048, K=64)
        k_cvt<<<(DI*DR/8 + 255)/256, 256>>>(Wdt, p_wf, DI*DR);
        k_mma<EPI_SOFTPLUS><<<dim3(TT/128, DI/128, 1), 256, SMEM_DYN>>>(
            p_xdf, 96, p_wf, DR, p_dlt, DI, TT, DI, DR, nullptr);

        k_scan<<<(BB*DI)/16, 256>>>(Al, Dpi);

        // out-proj split-K x2: partials then reduce+residual
        k_cvt<<<(DM*DI/8 + 255)/256, 256>>>(Wo, p_wf, DM*DI);
        k_mma<EPI_NONE><<<dim3(TT/128, DM/128, 2), 256, SMEM_DYN>>>(
            p_yf, DI, p_wf, DI, p_part, DM, TT, DM, DI/2, nullptr);
        k_redadd<<<(TT*DM + 255)/256, 256>>>(p_part);
    }

    // final norm + logits (2048 x 32000, K=1024)
    k_cvt<<<(VOCAB*DM/8 + 255)/256, 256>>>(emb, p_ef, VOCAB*DM);
    k_rmsnorm<<<TT, 256>>>(p_x, norm_f_w, p_xnf);
    k_mma<EPI_NONE><<<dim3(TT/128, VOCAB/128, 1), 256, SMEM_DYN>>>(
        p_xnf, DM, p_ef, DM, out, VOCAB, TT, VOCAB, DM, nullptr);
}

// round 10
// speedup vs baseline: 1.7544x; 1.0304x over previous
#include <cuda_runtime.h>
#include <cuda_fp16.h>
#include <cuda_bf16.h>
#include <cstdint>

// ---------------- problem constants ----------------
#define DM     1024
#define NLAYER 2
#define VOCAB  32000
#define DS     16
#define DI     2048
#define DR     64
#define DC     4
#define BB     2
#define LL     1024
#define TT     (BB*LL)

// ---------------- device scratch (fp32) ----------------
__device__ float g_x   [TT*DM];
__device__ float g_ir  [TT*2*DI];
__device__ float g_u   [TT*DI];
__device__ float g_xdbl[TT*96];
__device__ float g_dlt [TT*DI];
__device__ float g_part[2*TT*DM];    // split-K partials (covers 8*TT*96 too)

// ---------------- fp16 buffers ----------------
__device__ __half g_emb_f[VOCAB*DM];
__device__ __half g_wlr [NLAYER*2*DI*DM];
__device__ __half g_wx  [NLAYER*96*DI];
__device__ __half g_wdt [NLAYER*DI*DR];
__device__ __half g_wo  [NLAYER*DM*DI];
__device__ __half g_xn_f [TT*DM];
__device__ __half g_u_f  [TT*DI];
__device__ __half g_xd_f [TT*96];
__device__ __half g_y_f  [TT*DI];

// ---------------- helpers ----------------
static __device__ __forceinline__ uint32_t s2u(const void* p) {
    uint32_t a;
    asm("{ .reg .u64 t; cvta.to.shared.u64 t, %1; cvt.u32.u64 %0, t; }" : "=r"(a) : "l"(p));
    return a;
}
static __device__ __forceinline__ void cp16(uint32_t s, const void* g, bool pred) {
    int sz = pred ? 16 : 0;
    asm volatile("cp.async.cg.shared.global [%0], [%1], 16, %2;" :: "r"(s), "l"(g), "r"(sz));
}
#define CP_COMMIT() asm volatile("cp.async.commit_group;" ::: "memory")
#define CP_WAIT1()  asm volatile("cp.async.wait_group 1;"  ::: "memory")

#define LDSM4(r, addr) asm volatile( \
    "ldmatrix.sync.aligned.m8n8.x4.shared.b16 {%0,%1,%2,%3}, [%4];" \
    : "=r"((r)[0]),"=r"((r)[1]),"=r"((r)[2]),"=r"((r)[3]) : "r"(addr))
#define MMA(d, a, b) asm volatile( \
    "mma.sync.aligned.m16n8k16.row.col.f32.f16.f16.f32 " \
    "{%0,%1,%2,%3},{%4,%5,%6,%7},{%8,%9},{%0,%1,%2,%3};" \
    : "+f"((d)[0]),"+f"((d)[1]),"+f"((d)[2]),"+f"((d)[3]) \
    : "r"((a)[0]),"r"((a)[1]),"r"((a)[2]),"r"((a)[3]),"r"((b)[0]),"r"((b)[1]))

// ---------------- mega convert: all weights fp32 -> fp16, one launch ----------------
#define NSEG 11
struct CvtJobs {
    const float* src[NSEG];
    __half*      dst[NSEG];
    int          cum[NSEG+1];   // cumulative vec16 counts
};

__global__ void k_cvt_all(CvtJobs J) {
    int total = J.cum[NSEG];
    for (int v = blockIdx.x * blockDim.x + threadIdx.x; v < total;
         v += gridDim.x * blockDim.x) {
        int seg = 0;
        #pragma unroll
        for (int s = 1; s < NSEG; s++) seg += (v >= J.cum[s]) ? 1 : 0;
        int local = v - J.cum[seg];
        const float4* sp = reinterpret_cast<const float4*>(J.src[seg] + (size_t)local*16);
        __half* dp = J.dst[seg] + (size_t)local*16;
        float4 a = sp[0], b = sp[1], c = sp[2], d = sp[3];
        __half2 h0, h1, h2, h3, h4, h5, h6, h7;
        h0.x = __float2half_rn(a.x); h0.y = __float2half_rn(a.y);
        h1.x = __float2half_rn(a.z); h1.y = __float2half_rn(a.w);
        h2.x = __float2half_rn(b.x); h2.y = __float2half_rn(b.y);
        h3.x = __float2half_rn(b.z); h3.y = __float2half_rn(b.w);
        h4.x = __float2half_rn(c.x); h4.y = __float2half_rn(c.y);
        h5.x = __float2half_rn(c.z); h5.y = __float2half_rn(c.w);
        h6.x = __float2half_rn(d.x); h6.y = __float2half_rn(d.y);
        h7.x = __float2half_rn(d.z); h7.y = __float2half_rn(d.w);
        uint4 o0, o1;
        o0.x = *reinterpret_cast<uint32_t*>(&h0); o0.y = *reinterpret_cast<uint32_t*>(&h1);
        o0.z = *reinterpret_cast<uint32_t*>(&h2); o0.w = *reinterpret_cast<uint32_t*>(&h3);
        o1.x = *reinterpret_cast<uint32_t*>(&h4); o1.y = *reinterpret_cast<uint32_t*>(&h5);
        o1.z = *reinterpret_cast<uint32_t*>(&h6); o1.w = *reinterpret_cast<uint32_t*>(&h7);
        *reinterpret_cast<uint4*>(dp)     = o0;
        *reinterpret_cast<uint4*>(dp + 8) = o1;
    }
}

// ---------------- embed ----------------
__global__ void k_embed(const int* __restrict__ ids, const float* __restrict__ emb) {
    int t = blockIdx.x;
    int id = ids[t];
    for (int c = threadIdx.x; c < DM; c += blockDim.x)
        g_x[t*DM + c] = emb[id*DM + c];
}

// ---------------- rmsnorm -> fp16 ----------------
__global__ void k_rmsnorm(const float* __restrict__ x, const float* __restrict__ w,
                          __half* __restrict__ of) {
    int t = blockIdx.x;
    const float* xr = x + t*DM;
    float s = 0.f;
    for (int c = threadIdx.x; c < DM; c += blockDim.x) { float v = xr[c]; s += v*v; }
    for (int o = 16; o > 0; o >>= 1) s += __shfl_xor_sync(0xffffffffu, s, o);
    __shared__ float red[8];
    int wid = threadIdx.x >> 5, lid = threadIdx.x & 31;
    if (lid == 0) red[wid] = s;
    __syncthreads();
    if (wid == 0) {
        float v = (lid < (blockDim.x >> 5)) ? red[lid] : 0.f;
        for (int o = 4; o > 0; o >>= 1) v += __shfl_xor_sync(0xffffffffu, v, o);
        if (lid == 0) red[0] = v;
    }
    __syncthreads();
    float scale = rsqrtf(red[0] / (float)DM + 1e-5f);
    for (int c = threadIdx.x; c < DM; c += blockDim.x)
        of[t*DM + c] = __float2half_rn(xr[c] * scale * w[c]);
}

// ---------------- HMMA GEMM, BK=64, 3-stage, split-K via blockIdx.z ----------------
#define EPI_NONE     0
#define EPI_SOFTPLUS 1
#define EPI_RESADD   2

#define TILE_B   16384         // 128 rows x 128 bytes (BK=64 fp16)
#define OFF_A    0
#define OFF_B    (TILE_B)
#define STAGE_B  (2*TILE_B)    // 32 KB
#define NSTAGE   3
#define SMEM_DYN (NSTAGE*STAGE_B)   // 96 KB

// swizzle: 16B chunk c (0-7) of row r -> c ^ (r & 7)
__device__ __forceinline__ void load_stage(uint32_t sbase,
        const __half* __restrict__ A, int lda, int m0,
        const __half* __restrict__ Bf, int ldb, int n0, int N, int k0, int tid) {
    #pragma unroll
    for (int it = 0; it < 4; it++) {
        int i = tid + it*256;
        int r = i >> 3;
        int c = i & 7;
        uint32_t off = r*128 + ((c ^ (r & 7)) << 4);
        size_t ga = (size_t)(m0 + r)*lda + k0 + c*8;
        cp16(sbase + OFF_A + off, A + ga, true);
        bool bp = (n0 + r) < N;
        size_t gb = (size_t)(bp ? (n0 + r) : 0)*ldb + k0 + c*8;
        cp16(sbase + OFF_B + off, Bf + gb, bp);
    }
}

template<int EPI>
__global__ void __launch_bounds__(256, 2) k_mma(
        const __half* __restrict__ A, int lda,
        const __half* __restrict__ Bf, int ldb,
        float* __restrict__ C, int ldc, int M, int N, int Kslice,
        const float* __restrict__ R) {
    extern __shared__ __align__(1024) char smem[];
    const uint32_t sb = s2u(smem);
    const int tid = threadIdx.x, lane = tid & 31, wid = tid >> 5;
    const int wm = wid >> 2, wn = wid & 3;       // 2x4 warps, 64x32 each
    const int m0 = blockIdx.x * 128, n0 = blockIdx.y * 128;
    const int z = blockIdx.z;
    A  += (size_t)z * Kslice;
    Bf += (size_t)z * Kslice;
    C  += (size_t)z * M * ldc;

    float acc[4][4][4];
    #pragma unroll
    for (int a = 0; a < 4; a++)
        #pragma unroll
        for (int b = 0; b < 4; b++)
            #pragma unroll
            for (int c = 0; c < 4; c++) acc[a][b][c] = 0.f;

    const int NC = Kslice / 64;
    load_stage(sb + 0*STAGE_B, A, lda, m0, Bf, ldb, n0, N, 0, tid);
    CP_COMMIT();
    if (NC > 1)
        load_stage(sb + 1*STAGE_B, A, lda, m0, Bf, ldb, n0, N, 64, tid);
    CP_COMMIT();

    const int arow  = lane & 15;
    const int acb16 = (lane >> 4) & 1;
    const int brow  = lane & 7;
    const int bnt   = (lane >> 4) & 1;
    const int bkh   = (lane >> 3) & 1;

    int stage = 0;
    for (int c = 0; c < NC; c++) {
        CP_WAIT1();
        __syncthreads();
        if (c + 2 < NC) {
            int s2 = stage + 2; if (s2 >= NSTAGE) s2 -= NSTAGE;
            load_stage(sb + s2*STAGE_B, A, lda, m0, Bf, ldb, n0, N, (c + 2)*64, tid);
        }
        CP_COMMIT();

        uint32_t st = sb + stage*STAGE_B;
        #pragma unroll
        for (int kk = 0; kk < 4; kk++) {
            uint32_t bf[4][2], af[4][4];
            #pragma unroll
            for (int p = 0; p < 2; p++) {
                int r = wn*32 + (p*2 + bnt)*8 + brow;
                uint32_t off = r*128 + (((kk*2 + bkh) ^ (r & 7)) << 4);
                uint32_t t[4];
                LDSM4(t, st + OFF_B + off);
                bf[2*p][0] = t[0]; bf[2*p][1] = t[1];
                bf[2*p+1][0] = t[2]; bf[2*p+1][1] = t[3];
            }
            #pragma unroll
            for (int mt = 0; mt < 4; mt++) {
                int r = wm*64 + mt*16 + arow;
                uint32_t off = r*128 + (((kk*2 + acb16) ^ (r & 7)) << 4);
                LDSM4(af[mt], st + OFF_A + off);
            }
            #pragma unroll
            for (int mt = 0; mt < 4; mt++)
                #pragma unroll
                for (int nt = 0; nt < 4; nt++)
                    MMA(acc[mt][nt], af[mt], bf[nt]);
        }
        stage++; if (stage >= NSTAGE) stage = 0;
    }

    #pragma unroll
    for (int mt = 0; mt < 4; mt++) {
        #pragma unroll
        for (int nt = 0; nt < 4; nt++) {
            int row = m0 + wm*64 + mt*16 + (lane >> 2);
            int col = n0 + wn*32 + nt*8 + (lane & 3)*2;
            if (col < N) {
                #pragma unroll
                for (int h = 0; h < 2; h++) {
                    int rr = row + h*8;
                    float v0 = acc[mt][nt][2*h + 0];
                    float v1 = acc[mt][nt][2*h + 1];
                    if (EPI == EPI_SOFTPLUS) {
                        v0 = (v0 > 20.f) ? v0 : log1pf(expf(v0));
                        v1 = (v1 > 20.f) ? v1 : log1pf(expf(v1));
                    }
                    if (EPI == EPI_RESADD) {
                        v0 += R[(size_t)rr*ldc + col];
                        v1 += R[(size_t)rr*ldc + col + 1];
                    }
                    *reinterpret_cast<float2*>(&C[(size_t)rr*ldc + col]) = make_float2(v0, v1);
                }
            }
        }
    }
}

// ---------------- split-K reducers ----------------
__global__ void k_redx(const float* __restrict__ part) {
    int i = blockIdx.x * blockDim.x + threadIdx.x;
    if (i >= TT*96) return;
    float s = 0.f;
    #pragma unroll
    for (int z = 0; z < 8; z++) s += part[(size_t)z*TT*96 + i];
    g_xdbl[i] = s;
    g_xd_f[i] = __float2half_rn(s);
}
__global__ void k_redadd(const float* __restrict__ part) {
    int i = blockIdx.x * blockDim.x + threadIdx.x;
    if (i >= TT*DM) return;
    g_x[i] = part[i] + part[(size_t)TT*DM + i] + g_x[i];
}

// ---------------- depthwise causal conv + bias + SiLU ----------------
__global__ void k_conv_silu(const float* __restrict__ cw, const float* __restrict__ cb) {
    int idx = blockIdx.x * blockDim.x + threadIdx.x;
    if (idx >= TT*DI) return;
    int d = idx % DI;
    int l = (idx / DI) % LL;
    int b = idx / (DI*LL);
    float acc = cb[d];
    #pragma unroll
    for (int j = 0; j < DC; j++) {
        int ll = l - (DC-1) + j;
        if (ll >= 0) acc = fmaf(cw[d*DC + j], g_ir[((size_t)b*LL + ll)*(2*DI) + d], acc);
    }
    float s = acc / (1.f + __expf(-acc));
    g_u[idx] = s;
    g_u_f[idx] = __float2half_rn(s);
}

// ---------------- selective scan + gate, 4-step batched ----------------
__global__ void k_scan(const float* __restrict__ A_log, const float* __restrict__ Dp) {
    int lane = threadIdx.x & 15;
    int grp  = threadIdx.x >> 4;
    int ch   = blockIdx.x * 16 + grp;
    int b = ch / DI, d = ch % DI;

    float An = -__expf(A_log[d*DS + lane]);
    float Dv = Dp[d];
    float xs = 0.f;

    for (int l0 = 0; l0 < LL; l0 += 4) {
        float dlt[4], uu[4], Bn[4], Cn[4], dA[4], yv[4];
        #pragma unroll
        for (int j = 0; j < 4; j++) {
            size_t tok = (size_t)(b*LL + l0 + j);
            dlt[j] = g_dlt[tok*DI + d];
            uu[j]  = g_u  [tok*DI + d];
            Bn[j]  = g_xdbl[tok*96 + 64 + lane];
            Cn[j]  = g_xdbl[tok*96 + 80 + lane];
        }
        #pragma unroll
        for (int j = 0; j < 4; j++) dA[j] = __expf(dlt[j] * An);
        #pragma unroll
        for (int j = 0; j < 4; j++) {
            xs = fmaf(dA[j], xs, dlt[j] * uu[j] * Bn[j]);
            yv[j] = xs * Cn[j];
        }
        #pragma unroll
        for (int o = 8; o > 0; o >>= 1) {
            #pragma unroll
            for (int j = 0; j < 4; j++)
                yv[j] += __shfl_xor_sync(0xffffffffu, yv[j], o);
        }
        if (lane == 0) {
            #pragma unroll
            for (int j = 0; j < 4; j++) {
                size_t tok = (size_t)(b*LL + l0 + j);
                float r = g_ir[tok*(2*DI) + DI + d];
                float gate = r / (1.f + __expf(-r));
                g_y_f[tok*DI + d] = __float2half_rn((yv[j] + uu[j] * Dv) * gate);
            }
        }
    }
}

// ---------------- launch ----------------
extern "C" void kernel_launch(void* const* d_in, const int* in_sizes, int n_in,
                              void* d_out, int out_size) {
    const int*   ids      = (const int*)  d_in[0];
    const float* emb      = (const float*)d_in[1];
    const float* norm_f_w = (const float*)d_in[2];
    const float* W_in_l   = (const float*)d_in[3];
    const float* W_in_r   = (const float*)d_in[4];
    const float* conv_w   = (const float*)d_in[5];
    const float* conv_b   = (const float*)d_in[6];
    const float* W_x      = (const float*)d_in[7];
    const float* W_dt     = (const float*)d_in[8];
    const float* A_log    = (const float*)d_in[9];
    const float* Dp       = (const float*)d_in[10];
    const float* W_out    = (const float*)d_in[11];
    const float* norm_w   = (const float*)d_in[12];
    float* out = (float*)d_out;

    float *p_x, *p_ir, *p_u, *p_dlt, *p_part;
    cudaGetSymbolAddress((void**)&p_x,    g_x);
    cudaGetSymbolAddress((void**)&p_ir,   g_ir);
    cudaGetSymbolAddress((void**)&p_u,    g_u);
    cudaGetSymbolAddress((void**)&p_dlt,  g_dlt);
    cudaGetSymbolAddress((void**)&p_part, g_part);

    __half *p_ef, *p_wlr, *p_wx, *p_wdt, *p_wo, *p_xnf, *p_uf, *p_xdf, *p_yf;
    cudaGetSymbolAddress((void**)&p_ef,  g_emb_f);
    cudaGetSymbolAddress((void**)&p_wlr, g_wlr);
    cudaGetSymbolAddress((void**)&p_wx,  g_wx);
    cudaGetSymbolAddress((void**)&p_wdt, g_wdt);
    cudaGetSymbolAddress((void**)&p_wo,  g_wo);
    cudaGetSymbolAddress((void**)&p_xnf, g_xn_f);
    cudaGetSymbolAddress((void**)&p_uf,  g_u_f);
    cudaGetSymbolAddress((void**)&p_xdf, g_xd_f);
    cudaGetSymbolAddress((void**)&p_yf,  g_y_f);

    cudaFuncSetAttribute(k_mma<EPI_NONE>,     cudaFuncAttributeMaxDynamicSharedMemorySize, SMEM_DYN);
    cudaFuncSetAttribute(k_mma<EPI_SOFTPLUS>, cudaFuncAttributeMaxDynamicSharedMemorySize, SMEM_DYN);
    cudaFuncSetAttribute(k_mma<EPI_RESADD>,   cudaFuncAttributeMaxDynamicSharedMemorySize, SMEM_DYN);

    // ---- mega convert job table ----
    CvtJobs J;
    int idx = 0, cum = 0;
    auto add = [&](const float* s, __half* d, int n) {
        J.src[idx] = s; J.dst[idx] = d; J.cum[idx] = cum; cum += n/16; idx++;
    };
    J.cum[0] = 0;
    add(emb, p_ef, VOCAB*DM);
    for (int i = 0; i < NLAYER; i++) {
        add(W_in_l + (size_t)i*DI*DM, p_wlr + (size_t)i*2*DI*DM,           DI*DM);
        add(W_in_r + (size_t)i*DI*DM, p_wlr + (size_t)i*2*DI*DM + DI*DM,   DI*DM);
        add(W_x    + (size_t)i*96*DI, p_wx  + (size_t)i*96*DI,             96*DI);
        add(W_dt   + (size_t)i*DI*DR, p_wdt + (size_t)i*DI*DR,             DI*DR);
        add(W_out  + (size_t)i*DM*DI, p_wo  + (size_t)i*DM*DI,             DM*DI);
    }
    J.cum[NSEG] = cum;

    k_cvt_all<<<2368, 256>>>(J);                                   // 0
    k_embed<<<TT, 256>>>(ids, emb);                                // 1

    for (int i = 0; i < NLAYER; i++) {
        const float* cw  = conv_w + (size_t)i*DI*DC;
        const float* cb  = conv_b + (size_t)i*DI;
        const float* Al  = A_log  + (size_t)i*DI*DS;
        const float* Dpi = Dp     + (size_t)i*DI;
        const float* nw  = norm_w + (size_t)i*DM;
        __half* wlr = p_wlr + (size_t)i*2*DI*DM;
        __half* wx  = p_wx  + (size_t)i*96*DI;
        __half* wdt = p_wdt + (size_t)i*DI*DR;
        __half* wo  = p_wo  + (size_t)i*DM*DI;

        k_rmsnorm<<<TT, 256>>>(p_x, nw, p_xnf);                    // 2 (i=0)
        // 3 (i=0): fused in-proj GEMM <-- ncu capture
        k_mma<EPI_NONE><<<dim3(TT/128, 2*DI/128, 1), 256, SMEM_DYN>>>(
            p_xnf, DM, wlr, DM, p_ir, 2*DI, TT, 2*DI, DM, nullptr);

        k_conv_silu<<<(TT*DI + 255)/256, 256>>>(cw, cb);

        // x_dbl = u @ Wx^T  split-K x8 (Kslice=256)
        k_mma<EPI_NONE><<<dim3(TT/128, 1, 8), 256, SMEM_DYN>>>(
            p_uf, DI, wx, DI, p_part, 96, TT, 96, DI/8, nullptr);
        k_redx<<<(TT*96 + 255)/256, 256>>>(p_part);

        // delta = softplus(x_dbl[:, :64] @ Wdt^T)  (K=64)
        k_mma<EPI_SOFTPLUS><<<dim3(TT/128, DI/128, 1), 256, SMEM_DYN>>>(
            p_xdf, 96, wdt, DR, p_dlt, DI, TT, DI, DR, nullptr);

        k_scan<<<(BB*DI)/16, 256>>>(Al, Dpi);

        // out-proj split-K x2 (Kslice=1024) + residual reduce
        k_mma<EPI_NONE><<<dim3(TT/128, DM/128, 2), 256, SMEM_DYN>>>(
            p_yf, DI, wo, DI, p_part, DM, TT, DM, DI/2, nullptr);
        k_redadd<<<(TT*DM + 255)/256, 256>>>(p_part);
    }

    // final norm + logits
    k_rmsnorm<<<TT, 256>>>(p_x, norm_f_w, p_xnf);
    k_mma<EPI_NONE><<<dim3(TT/128, VOCAB/128, 1), 256, SMEM_DYN>>>(
        p_xnf, DM, p_ef, DM, out, VOCAB, TT, VOCAB, DM, nullptr);
}